// round 6
// baseline (speedup 1.0000x reference)
#include <cuda_runtime.h>
#include <math.h>
#include <stdint.h>

// ---------------- problem constants ----------------
#define B_     2
#define LQ_    21760
#define M_     (B_ * LQ_)      // 43520
#define C_     256
#define NHEAD_ 8
#define NS_    4
#define NL_    6
#define FF_    1024
#define NQKV   640             // 256 (v) + 256 (off) + 128 (att logits)

__device__ __constant__ int d_scH[4]   = {128, 64, 32, 16};
__device__ __constant__ int d_scW[4]   = {128, 64, 32, 16};
__device__ __constant__ int d_scSt[4]  = {0, 16384, 20480, 21504};

// ---------------- scratch (device globals; no allocation) ----------------
__device__ float g_xp  [(size_t)M_ * C_];    // x + pos (exact, LN1 residual)
__device__ float g_xpT [(size_t)M_ * C_];    // tf32-rounded xp (GEMM A input)
__device__ float g_qkv [(size_t)M_ * NQKV];  // fused v|off|logits
__device__ float g_samp[(size_t)M_ * C_];    // sampled value (tf32-rounded)
__device__ float g_a   [(size_t)M_ * C_];    // attn out proj (exact)
__device__ float g_x   [(size_t)M_ * C_];    // post-LN1 (exact)
__device__ float g_xT  [(size_t)M_ * C_];    // tf32-rounded post-LN1
__device__ float g_h   [(size_t)M_ * FF_];   // FFN hidden (tf32-rounded)
__device__ float g_f   [(size_t)M_ * C_];    // FFN out (exact)
// pre-rounded / packed weights
__device__ float g_wq  [(size_t)NL_ * C_ * NQKV];
__device__ float g_bq  [(size_t)NL_ * NQKV];
__device__ float g_wo  [(size_t)NL_ * C_ * C_];
__device__ float g_w1  [(size_t)NL_ * C_ * FF_];
__device__ float g_w2  [(size_t)NL_ * FF_ * C_];

__device__ __forceinline__ uint32_t f2tf32(float x) {
    uint32_t r;
    asm("cvt.rna.tf32.f32 %0, %1;" : "=r"(r) : "f"(x));
    return r;
}
__device__ __forceinline__ float rndt(float x) { return __uint_as_float(f2tf32(x)); }

// ---------------- weight prep ----------------
__global__ void round_kernel(const float* __restrict__ src, float* __restrict__ dst, int n4) {
    int i = blockIdx.x * blockDim.x + threadIdx.x;
    if (i >= n4) return;
    float4 v = ((const float4*)src)[i];
    v.x = rndt(v.x); v.y = rndt(v.y); v.z = rndt(v.z); v.w = rndt(v.w);
    ((float4*)dst)[i] = v;
}

__global__ void pack_qkv_kernel(const float* __restrict__ Wv, const float* __restrict__ Woff,
                                const float* __restrict__ Wat,
                                const float* __restrict__ bv, const float* __restrict__ boff,
                                const float* __restrict__ bat,
                                float* __restrict__ wq, float* __restrict__ bq) {
    int idx = blockIdx.x * blockDim.x + threadIdx.x;
    const int total = NL_ * C_ * NQKV;
    if (idx < total) {
        const int c = idx % NQKV;
        const int k = (idx / NQKV) % C_;
        const int l = idx / (NQKV * C_);
        float v;
        if (c < 256)      v = Wv  [((size_t)l * C_ + k) * 256 + c];
        else if (c < 512) v = Woff[((size_t)l * C_ + k) * 256 + (c - 256)];
        else              v = Wat [((size_t)l * C_ + k) * 128 + (c - 512)];
        wq[idx] = rndt(v);
    }
    if (idx < NL_ * NQKV) {
        const int c = idx % NQKV;
        const int l = idx / NQKV;
        float v;
        if (c < 256)      v = bv  [l * 256 + c];
        else if (c < 512) v = boff[l * 256 + (c - 256)];
        else              v = bat [l * 128 + (c - 512)];
        bq[idx] = v;
    }
}

// ---------------- layer-0 prep: xp = src + pos (exact + rounded) -----------
__global__ void add0_kernel(const float* __restrict__ a, const float* __restrict__ b,
                            float* __restrict__ out, float* __restrict__ outT, int n4) {
    int i = blockIdx.x * blockDim.x + threadIdx.x;
    if (i >= n4) return;
    float4 va = ((const float4*)a)[i];
    float4 vb = ((const float4*)b)[i];
    va.x += vb.x; va.y += vb.y; va.z += vb.z; va.w += vb.w;
    ((float4*)out)[i] = va;
    ((float4*)outT)[i] = make_float4(rndt(va.x), rndt(va.y), rndt(va.z), rndt(va.w));
}

// ---------------- tf32 tensor-core GEMM, cp.async 3-stage ----------------
#define BM 128
#define BN 128
#define BK 32
#define ASTRIDE 36
#define BSTRIDE 136
#define ASZ (BM * ASTRIDE)
#define BSZ (BK * BSTRIDE)
#define STAGEF (ASZ + BSZ)
#define NSTAGE 3
#define GEMM_SMEM (NSTAGE * STAGEF * 4)   // 107520 bytes

__device__ __forceinline__ void cpa16(float* dst, const float* src) {
    uint32_t d = (uint32_t)__cvta_generic_to_shared(dst);
    asm volatile("cp.async.cg.shared.global [%0], [%1], 16;" :: "r"(d), "l"(src));
}

__global__ __launch_bounds__(256, 2)
void tf32gemm_kernel(const float* __restrict__ A, const float* __restrict__ W,
                     const float* __restrict__ bias, float* __restrict__ Cout,
                     int N, int Kd, int relu, int roundOut) {
    extern __shared__ __align__(16) float sm[];

    const int tid  = threadIdx.x;
    const int warp = tid >> 5;
    const int lane = tid & 31;
    const int m0 = (warp >> 2) * 64;
    const int n0 = (warp & 3) * 32;
    const int bx = blockIdx.x, by = blockIdx.y;

    const int lr = tid >> 3;
    const int lc = (tid & 7) * 4;

    const float* Ag = A + (size_t)(by * BM) * Kd;
    const float* Wg = W + (size_t)bx * BN;

    float acc[4][4][4];
#pragma unroll
    for (int mi = 0; mi < 4; mi++)
#pragma unroll
        for (int nf = 0; nf < 4; nf++)
#pragma unroll
            for (int r = 0; r < 4; r++) acc[mi][nf][r] = 0.f;

    const int NK = Kd / BK;

    // prologue: issue stages 0, 1
#pragma unroll
    for (int s = 0; s < 2; s++) {
        if (s < NK) {
            float* as = sm + s * STAGEF;
            float* bs = as + ASZ;
            const int k0 = s * BK;
#pragma unroll
            for (int p = 0; p < 4; p++) {
                const int row = p * 32 + lr;
                cpa16(as + row * ASTRIDE + lc, Ag + (size_t)row * Kd + k0 + lc);
            }
#pragma unroll
            for (int p = 0; p < 4; p++) {
                const int col = p * 32 + lc;
                cpa16(bs + lr * BSTRIDE + col, Wg + (size_t)(k0 + lr) * N + col);
            }
            asm volatile("cp.async.commit_group;");
        }
    }

    const int ar = lane >> 2;
    const int ak = lane & 3;

    for (int i = 0; i < NK; i++) {
        asm volatile("cp.async.wait_group 1;");
        __syncthreads();

        if (i + 2 < NK) {
            const int k0 = (i + 2) * BK;
            float* as = sm + ((i + 2) % NSTAGE) * STAGEF;
            float* bs = as + ASZ;
#pragma unroll
            for (int p = 0; p < 4; p++) {
                const int row = p * 32 + lr;
                cpa16(as + row * ASTRIDE + lc, Ag + (size_t)row * Kd + k0 + lc);
            }
#pragma unroll
            for (int p = 0; p < 4; p++) {
                const int col = p * 32 + lc;
                cpa16(bs + lr * BSTRIDE + col, Wg + (size_t)(k0 + lr) * N + col);
            }
            asm volatile("cp.async.commit_group;");
        }

        const float* as = sm + (i % NSTAGE) * STAGEF;
        const float* bs = as + ASZ;

#pragma unroll
        for (int kk = 0; kk < BK; kk += 8) {
            uint32_t a[4][4];
            uint32_t b[4][2];
#pragma unroll
            for (int mi = 0; mi < 4; mi++) {
                const int r = m0 + mi * 16 + ar;
                a[mi][0] = __float_as_uint(as[(r    ) * ASTRIDE + kk + ak    ]);
                a[mi][1] = __float_as_uint(as[(r + 8) * ASTRIDE + kk + ak    ]);
                a[mi][2] = __float_as_uint(as[(r    ) * ASTRIDE + kk + ak + 4]);
                a[mi][3] = __float_as_uint(as[(r + 8) * ASTRIDE + kk + ak + 4]);
            }
#pragma unroll
            for (int nf = 0; nf < 4; nf++) {
                const int c = n0 + nf * 8 + ar;
                b[nf][0] = __float_as_uint(bs[(kk + ak    ) * BSTRIDE + c]);
                b[nf][1] = __float_as_uint(bs[(kk + ak + 4) * BSTRIDE + c]);
            }
#pragma unroll
            for (int mi = 0; mi < 4; mi++)
#pragma unroll
                for (int nf = 0; nf < 4; nf++) {
                    asm volatile(
                        "mma.sync.aligned.m16n8k8.row.col.f32.tf32.tf32.f32 "
                        "{%0,%1,%2,%3}, {%4,%5,%6,%7}, {%8,%9}, {%0,%1,%2,%3};"
                        : "+f"(acc[mi][nf][0]), "+f"(acc[mi][nf][1]),
                          "+f"(acc[mi][nf][2]), "+f"(acc[mi][nf][3])
                        : "r"(a[mi][0]), "r"(a[mi][1]), "r"(a[mi][2]), "r"(a[mi][3]),
                          "r"(b[nf][0]), "r"(b[nf][1]));
                }
        }
    }

    // epilogue
    const int gr = lane >> 2;
    const int gc = (lane & 3) * 2;
#pragma unroll
    for (int mi = 0; mi < 4; mi++) {
#pragma unroll
        for (int nf = 0; nf < 4; nf++) {
            const int col = bx * BN + n0 + nf * 8 + gc;
            const float b0 = bias[col], b1 = bias[col + 1];
            const int row0 = by * BM + m0 + mi * 16 + gr;

            float2 v0 = make_float2(acc[mi][nf][0] + b0, acc[mi][nf][1] + b1);
            float2 v1 = make_float2(acc[mi][nf][2] + b0, acc[mi][nf][3] + b1);
            if (relu) {
                v0.x = fmaxf(v0.x, 0.f); v0.y = fmaxf(v0.y, 0.f);
                v1.x = fmaxf(v1.x, 0.f); v1.y = fmaxf(v1.y, 0.f);
            }
            if (roundOut) {
                v0.x = rndt(v0.x); v0.y = rndt(v0.y);
                v1.x = rndt(v1.x); v1.y = rndt(v1.y);
            }
            *(float2*)(Cout + (size_t)row0 * N + col)       = v0;
            *(float2*)(Cout + (size_t)(row0 + 8) * N + col) = v1;
        }
    }
}

// ---------------- deformable sampling with fused softmax -------------------
// grid = M; warp per head, lane = channel
__global__ void deform_kernel(const float* __restrict__ qkv,
                              const float* __restrict__ ref,
                              float* __restrict__ out) {
    const int q = blockIdx.x;
    const int h = threadIdx.x >> 5;
    const int d = threadIdx.x & 31;
    const int b = q / LQ_;

    // softmax over this head's 16 logits (every lane computes; broadcast loads)
    const float* lg = qkv + (size_t)q * NQKV + 512 + h * 16;
    float w[16];
    float mx = -1e30f;
#pragma unroll
    for (int i = 0; i < 16; i++) { w[i] = lg[i]; mx = fmaxf(mx, w[i]); }
    float s = 0.f;
#pragma unroll
    for (int i = 0; i < 16; i++) { w[i] = __expf(w[i] - mx); s += w[i]; }
    const float inv = 1.f / s;

    const float rx = ref[(size_t)q * 2 + 0];
    const float ry = ref[(size_t)q * 2 + 1];
    const float* offq = qkv + (size_t)q * NQKV + 256 + h * 32;

    float acc = 0.f;
#pragma unroll
    for (int l = 0; l < 4; l++) {
        const int Hl = d_scH[l], Wl = d_scW[l], st = d_scSt[l];
        const float invW = 1.f / (float)Wl, invH = 1.f / (float)Hl;
        const float Wm1 = (float)(Wl - 1), Hm1 = (float)(Hl - 1);
        const float* vl = qkv + (size_t)(b * LQ_ + st) * NQKV + h * 32 + d;
#pragma unroll
        for (int k = 0; k < 4; k++) {
            const float ox = offq[l * 8 + k * 2 + 0];
            const float oy = offq[l * 8 + k * 2 + 1];
            const float ww = w[l * 4 + k] * inv;
            float x = (rx + ox * invW) * Wm1;
            float y = (ry + oy * invH) * Hm1;
            x = fminf(fmaxf(x, 0.f), Wm1);
            y = fminf(fmaxf(y, 0.f), Hm1);
            const float x0f = floorf(x), y0f = floorf(y);
            const int x0 = (int)x0f, y0 = (int)y0f;
            const int x1 = min(x0 + 1, Wl - 1), y1 = min(y0 + 1, Hl - 1);
            const float wx = x - x0f, wy = y - y0f;
            const float v00 = vl[(size_t)(y0 * Wl + x0) * NQKV];
            const float v01 = vl[(size_t)(y0 * Wl + x1) * NQKV];
            const float v10 = vl[(size_t)(y1 * Wl + x0) * NQKV];
            const float v11 = vl[(size_t)(y1 * Wl + x1) * NQKV];
            const float top = v00 + wx * (v01 - v00);
            const float bot = v10 + wx * (v11 - v10);
            acc = fmaf(ww, top + wy * (bot - top), acc);
        }
    }
    out[(size_t)q * C_ + h * 32 + d] = rndt(acc);
}

// ---------------- fused residual + layernorm (vectorized) ------------------
// out = LN(a+b)*gamma+beta [+ pos]; optional rounded copy.
__global__ void ln_kernel(const float* __restrict__ a, const float* __restrict__ b,
                          const float* __restrict__ gamma, const float* __restrict__ beta,
                          const float* __restrict__ pos,
                          float* __restrict__ out, float* __restrict__ outT) {
    const int row = blockIdx.x * 8 + (threadIdx.x >> 5);
    const int lane = threadIdx.x & 31;
    const size_t base = (size_t)row * C_ + lane * 8;

    float vals[8];
    {
        float4 a0 = *(const float4*)(a + base);
        float4 a1 = *(const float4*)(a + base + 4);
        float4 b0 = *(const float4*)(b + base);
        float4 b1 = *(const float4*)(b + base + 4);
        vals[0] = a0.x + b0.x; vals[1] = a0.y + b0.y;
        vals[2] = a0.z + b0.z; vals[3] = a0.w + b0.w;
        vals[4] = a1.x + b1.x; vals[5] = a1.y + b1.y;
        vals[6] = a1.z + b1.z; vals[7] = a1.w + b1.w;
    }
    float s = 0.f;
#pragma unroll
    for (int i = 0; i < 8; i++) s += vals[i];
#pragma unroll
    for (int o = 16; o > 0; o >>= 1) s += __shfl_xor_sync(0xffffffffu, s, o);
    const float mean = s * (1.f / 256.f);
    float vs = 0.f;
#pragma unroll
    for (int i = 0; i < 8; i++) {
        const float dlt = vals[i] - mean;
        vs += dlt * dlt;
    }
#pragma unroll
    for (int o = 16; o > 0; o >>= 1) vs += __shfl_xor_sync(0xffffffffu, vs, o);
    const float rstd = rsqrtf(vs * (1.f / 256.f) + 1e-5f);

    const int c = lane * 8;
    float4 g0 = *(const float4*)(gamma + c);
    float4 g1 = *(const float4*)(gamma + c + 4);
    float4 t0 = *(const float4*)(beta + c);
    float4 t1 = *(const float4*)(beta + c + 4);
    float o[8];
    o[0] = (vals[0] - mean) * rstd * g0.x + t0.x;
    o[1] = (vals[1] - mean) * rstd * g0.y + t0.y;
    o[2] = (vals[2] - mean) * rstd * g0.z + t0.z;
    o[3] = (vals[3] - mean) * rstd * g0.w + t0.w;
    o[4] = (vals[4] - mean) * rstd * g1.x + t1.x;
    o[5] = (vals[5] - mean) * rstd * g1.y + t1.y;
    o[6] = (vals[6] - mean) * rstd * g1.z + t1.z;
    o[7] = (vals[7] - mean) * rstd * g1.w + t1.w;

    if (pos) {
        float4 p0 = *(const float4*)(pos + base);
        float4 p1 = *(const float4*)(pos + base + 4);
        o[0] += p0.x; o[1] += p0.y; o[2] += p0.z; o[3] += p0.w;
        o[4] += p1.x; o[5] += p1.y; o[6] += p1.z; o[7] += p1.w;
    }
    *(float4*)(out + base)     = make_float4(o[0], o[1], o[2], o[3]);
    *(float4*)(out + base + 4) = make_float4(o[4], o[5], o[6], o[7]);
    if (outT) {
        *(float4*)(outT + base)     = make_float4(rndt(o[0]), rndt(o[1]), rndt(o[2]), rndt(o[3]));
        *(float4*)(outT + base + 4) = make_float4(rndt(o[4]), rndt(o[5]), rndt(o[6]), rndt(o[7]));
    }
}

// ---------------- launch ----------------
extern "C" void kernel_launch(void* const* d_in, const int* in_sizes, int n_in,
                              void* d_out, int out_size) {
    const float* src  = (const float*)d_in[0];
    const float* pos  = (const float*)d_in[1];
    const float* ref  = (const float*)d_in[2];
    const float* Woff = (const float*)d_in[3];
    const float* boff = (const float*)d_in[4];
    const float* Wat  = (const float*)d_in[5];
    const float* bat  = (const float*)d_in[6];
    const float* Wv   = (const float*)d_in[7];
    const float* bv   = (const float*)d_in[8];
    const float* Wo   = (const float*)d_in[9];
    const float* bo   = (const float*)d_in[10];
    const float* W1   = (const float*)d_in[11];
    const float* b1   = (const float*)d_in[12];
    const float* W2   = (const float*)d_in[13];
    const float* b2   = (const float*)d_in[14];
    const float* n1s  = (const float*)d_in[15];
    const float* n1b  = (const float*)d_in[16];
    const float* n2s  = (const float*)d_in[17];
    const float* n2b  = (const float*)d_in[18];
    float* outp = (float*)d_out;

    float *xp, *xpT, *qkv, *samp, *a, *x, *xT, *hbuf, *fbuf;
    float *wq, *bq, *wo, *w1, *w2;
    cudaGetSymbolAddress((void**)&xp,   g_xp);
    cudaGetSymbolAddress((void**)&xpT,  g_xpT);
    cudaGetSymbolAddress((void**)&qkv,  g_qkv);
    cudaGetSymbolAddress((void**)&samp, g_samp);
    cudaGetSymbolAddress((void**)&a,    g_a);
    cudaGetSymbolAddress((void**)&x,    g_x);
    cudaGetSymbolAddress((void**)&xT,   g_xT);
    cudaGetSymbolAddress((void**)&hbuf, g_h);
    cudaGetSymbolAddress((void**)&fbuf, g_f);
    cudaGetSymbolAddress((void**)&wq,   g_wq);
    cudaGetSymbolAddress((void**)&bq,   g_bq);
    cudaGetSymbolAddress((void**)&wo,   g_wo);
    cudaGetSymbolAddress((void**)&w1,   g_w1);
    cudaGetSymbolAddress((void**)&w2,   g_w2);

    cudaFuncSetAttribute(tf32gemm_kernel,
                         cudaFuncAttributeMaxDynamicSharedMemorySize, GEMM_SMEM);

    // weight prep
    {
        const int nq = NL_ * C_ * NQKV;
        pack_qkv_kernel<<<(nq + 255) / 256, 256>>>(Wv, Woff, Wat, bv, boff, bat, wq, bq);
        const int n_wo = NL_ * C_ * C_ / 4;
        round_kernel<<<(n_wo + 255) / 256, 256>>>(Wo, wo, n_wo);
        const int n_w1 = NL_ * C_ * FF_ / 4;
        round_kernel<<<(n_w1 + 255) / 256, 256>>>(W1, w1, n_w1);
        const int n_w2 = NL_ * FF_ * C_ / 4;
        round_kernel<<<(n_w2 + 255) / 256, 256>>>(W2, w2, n_w2);
    }

    const int n4 = M_ * C_ / 4;
    const dim3 gQKV(NQKV / BN, M_ / BM);
    const dim3 gN256(2, M_ / BM);
    const dim3 gN1024(8, M_ / BM);

    // layer 0 prep: xp = src + pos
    add0_kernel<<<(n4 + 255) / 256, 256>>>(src, pos, xp, xpT, n4);

    for (int i = 0; i < NL_; i++) {
        // fused qkv = xpT @ [Wv|Woff|Wat] + [bv|boff|bat]
        tf32gemm_kernel<<<gQKV, 256, GEMM_SMEM>>>(xpT, wq + (size_t)i * C_ * NQKV,
                                                  bq + (size_t)i * NQKV, qkv, NQKV, C_, 0, 0);
        // sampling with fused softmax
        deform_kernel<<<M_, 256>>>(qkv, ref, samp);
        // a = samp @ Wo + bo
        tf32gemm_kernel<<<gN256, 256, GEMM_SMEM>>>(samp, wo + (size_t)i * C_ * C_,
                                                   bo + (size_t)i * C_, a, 256, C_, 0, 0);
        // x = LN(xp + a)  (+ rounded copy for W1)
        ln_kernel<<<M_ / 8, 256>>>(xp, a, n1s + (size_t)i * C_, n1b + (size_t)i * C_,
                                   (const float*)nullptr, x, xT);
        // h = round(relu(xT @ W1 + b1))
        tf32gemm_kernel<<<gN1024, 256, GEMM_SMEM>>>(xT, w1 + (size_t)i * C_ * FF_,
                                                    b1 + (size_t)i * FF_, hbuf, FF_, C_, 1, 1);
        // f = h @ W2 + b2
        tf32gemm_kernel<<<gN256, 256, GEMM_SMEM>>>(hbuf, w2 + (size_t)i * FF_ * C_,
                                                   b2 + (size_t)i * C_, fbuf, 256, FF_, 0, 0);
        // LN2: last layer → pure LN to d_out; else fold +pos for next layer's xp
        if (i == NL_ - 1) {
            ln_kernel<<<M_ / 8, 256>>>(x, fbuf, n2s + (size_t)i * C_, n2b + (size_t)i * C_,
                                       (const float*)nullptr, outp, (float*)nullptr);
        } else {
            ln_kernel<<<M_ / 8, 256>>>(x, fbuf, n2s + (size_t)i * C_, n2b + (size_t)i * C_,
                                       pos, xp, xpT);
        }
    }
    (void)in_sizes; (void)n_in; (void)out_size;
}

// round 7
// speedup vs baseline: 1.0171x; 1.0171x over previous
#include <cuda_runtime.h>
#include <math.h>
#include <stdint.h>

// ---------------- problem constants ----------------
#define B_     2
#define LQ_    21760
#define M_     (B_ * LQ_)      // 43520
#define C_     256
#define NHEAD_ 8
#define NS_    4
#define NL_    6
#define FF_    1024
#define NQKV   640             // 256 (v) + 256 (off) + 128 (att logits)

__device__ __constant__ int d_scH[4]   = {128, 64, 32, 16};
__device__ __constant__ int d_scW[4]   = {128, 64, 32, 16};
__device__ __constant__ int d_scSt[4]  = {0, 16384, 20480, 21504};

// ---------------- scratch (device globals; no allocation) ----------------
__device__ float g_xp  [(size_t)M_ * C_];    // x + pos (exact, LN1 residual)
__device__ float g_xpT [(size_t)M_ * C_];    // tf32-rounded xp
__device__ float g_qkv [(size_t)M_ * NQKV];  // fused v|off|logits
__device__ float g_samp[(size_t)M_ * C_];    // sampled value (tf32-rounded)
__device__ float g_a   [(size_t)M_ * C_];    // attn out proj (exact)
__device__ float g_x   [(size_t)M_ * C_];    // post-LN1 (exact)
__device__ float g_xT  [(size_t)M_ * C_];    // tf32-rounded post-LN1
__device__ float g_h   [(size_t)M_ * FF_];   // FFN hidden (tf32-rounded)
__device__ float g_f   [(size_t)M_ * C_];    // FFN out (exact)
__device__ float g_wq  [(size_t)NL_ * C_ * NQKV];
__device__ float g_bq  [(size_t)NL_ * NQKV];
__device__ float g_wo  [(size_t)NL_ * C_ * C_];
__device__ float g_w1  [(size_t)NL_ * C_ * FF_];
__device__ float g_w2  [(size_t)NL_ * FF_ * C_];

__device__ __forceinline__ uint32_t f2tf32(float x) {
    uint32_t r;
    asm("cvt.rna.tf32.f32 %0, %1;" : "=r"(r) : "f"(x));
    return r;
}
__device__ __forceinline__ float rndt(float x) { return __uint_as_float(f2tf32(x)); }

// ---------------- weight prep ----------------
__global__ void round_kernel(const float* __restrict__ src, float* __restrict__ dst, int n4) {
    int i = blockIdx.x * blockDim.x + threadIdx.x;
    if (i >= n4) return;
    float4 v = ((const float4*)src)[i];
    v.x = rndt(v.x); v.y = rndt(v.y); v.z = rndt(v.z); v.w = rndt(v.w);
    ((float4*)dst)[i] = v;
}

__global__ void pack_qkv_kernel(const float* __restrict__ Wv, const float* __restrict__ Woff,
                                const float* __restrict__ Wat,
                                const float* __restrict__ bv, const float* __restrict__ boff,
                                const float* __restrict__ bat,
                                float* __restrict__ wq, float* __restrict__ bq) {
    int idx = blockIdx.x * blockDim.x + threadIdx.x;
    const int total = NL_ * C_ * NQKV;
    if (idx < total) {
        const int c = idx % NQKV;
        const int k = (idx / NQKV) % C_;
        const int l = idx / (NQKV * C_);
        float v;
        if (c < 256)      v = Wv  [((size_t)l * C_ + k) * 256 + c];
        else if (c < 512) v = Woff[((size_t)l * C_ + k) * 256 + (c - 256)];
        else              v = Wat [((size_t)l * C_ + k) * 128 + (c - 512)];
        wq[idx] = rndt(v);
    }
    if (idx < NL_ * NQKV) {
        const int c = idx % NQKV;
        const int l = idx / NQKV;
        float v;
        if (c < 256)      v = bv  [l * 256 + c];
        else if (c < 512) v = boff[l * 256 + (c - 256)];
        else              v = bat [l * 128 + (c - 512)];
        bq[idx] = v;
    }
}

// ---------------- layer-0 prep ----------------
__global__ void add0_kernel(const float* __restrict__ a, const float* __restrict__ b,
                            float* __restrict__ out, float* __restrict__ outT, int n4) {
    int i = blockIdx.x * blockDim.x + threadIdx.x;
    if (i >= n4) return;
    float4 va = ((const float4*)a)[i];
    float4 vb = ((const float4*)b)[i];
    va.x += vb.x; va.y += vb.y; va.z += vb.z; va.w += vb.w;
    ((float4*)out)[i] = va;
    ((float4*)outT)[i] = make_float4(rndt(va.x), rndt(va.y), rndt(va.z), rndt(va.w));
}

// ---------------- tf32 GEMM: 128x128x32 tile, 128 threads, warp 64x64 ------
#define BM 128
#define BN 128
#define BK 32
#define ASTRIDE 36
#define BSTRIDE 136
#define ASZ (BM * ASTRIDE)          // 4608
#define BSZ (BK * BSTRIDE)          // 4352
#define STAGEF (ASZ + BSZ)          // 8960 floats = 35840 B
#define NSTAGE 3
#define GEMM_SMEM (NSTAGE * STAGEF * 4)   // 107520 B

__device__ __forceinline__ void cpa16(float* dst, const float* src) {
    uint32_t d = (uint32_t)__cvta_generic_to_shared(dst);
    asm volatile("cp.async.cg.shared.global [%0], [%1], 16;" :: "r"(d), "l"(src));
}

__global__ __launch_bounds__(128, 2)
void tf32gemm_kernel(const float* __restrict__ A, const float* __restrict__ W,
                     const float* __restrict__ bias, float* __restrict__ Cout,
                     int N, int Kd, int relu, int roundOut) {
    extern __shared__ __align__(16) float sm[];

    const int tid  = threadIdx.x;
    const int warp = tid >> 5;
    const int lane = tid & 31;
    const int m0 = (warp >> 1) * 64;     // 2x2 warps, 64x64 each
    const int n0 = (warp & 1) * 64;
    const int bx = blockIdx.x, by = blockIdx.y;

    // loader indices (128 threads)
    const int alr = tid >> 3;            // 0..15 (A: row within 16-row pass)
    const int alc = (tid & 7) * 4;       // 0..28
    const int blr = tid >> 5;            // 0..3  (B: row within 4-row pass)
    const int blc = (tid & 31) * 4;      // 0..124

    const float* Ag = A + (size_t)(by * BM) * Kd;
    const float* Wg = W + (size_t)bx * BN;

    float acc[4][8][4];
#pragma unroll
    for (int mi = 0; mi < 4; mi++)
#pragma unroll
        for (int nf = 0; nf < 8; nf++)
#pragma unroll
            for (int r = 0; r < 4; r++) acc[mi][nf][r] = 0.f;

    const int NK = Kd / BK;

    // prologue: stages 0,1
#pragma unroll
    for (int s = 0; s < 2; s++) {
        if (s < NK) {
            float* as = sm + s * STAGEF;
            float* bs = as + ASZ;
            const int k0 = s * BK;
#pragma unroll
            for (int p = 0; p < 8; p++) {
                const int row = p * 16 + alr;
                cpa16(as + row * ASTRIDE + alc, Ag + (size_t)row * Kd + k0 + alc);
            }
#pragma unroll
            for (int p = 0; p < 8; p++) {
                const int row = p * 4 + blr;
                cpa16(bs + row * BSTRIDE + blc, Wg + (size_t)(k0 + row) * N + blc);
            }
            asm volatile("cp.async.commit_group;");
        }
    }

    const int ar = lane >> 2;
    const int ak = lane & 3;

    for (int i = 0; i < NK; i++) {
        asm volatile("cp.async.wait_group 1;");
        __syncthreads();

        if (i + 2 < NK) {
            const int k0 = (i + 2) * BK;
            float* as = sm + ((i + 2) % NSTAGE) * STAGEF;
            float* bs = as + ASZ;
#pragma unroll
            for (int p = 0; p < 8; p++) {
                const int row = p * 16 + alr;
                cpa16(as + row * ASTRIDE + alc, Ag + (size_t)row * Kd + k0 + alc);
            }
#pragma unroll
            for (int p = 0; p < 8; p++) {
                const int row = p * 4 + blr;
                cpa16(bs + row * BSTRIDE + blc, Wg + (size_t)(k0 + row) * N + blc);
            }
            asm volatile("cp.async.commit_group;");
        }

        const float* as = sm + (i % NSTAGE) * STAGEF;
        const float* bs = as + ASZ;

#pragma unroll
        for (int kk = 0; kk < BK; kk += 8) {
            uint32_t a[4][4];
            uint32_t b[8][2];
#pragma unroll
            for (int mi = 0; mi < 4; mi++) {
                const int r = m0 + mi * 16 + ar;
                a[mi][0] = __float_as_uint(as[(r    ) * ASTRIDE + kk + ak    ]);
                a[mi][1] = __float_as_uint(as[(r + 8) * ASTRIDE + kk + ak    ]);
                a[mi][2] = __float_as_uint(as[(r    ) * ASTRIDE + kk + ak + 4]);
                a[mi][3] = __float_as_uint(as[(r + 8) * ASTRIDE + kk + ak + 4]);
            }
#pragma unroll
            for (int nf = 0; nf < 8; nf++) {
                const int c = n0 + nf * 8 + ar;
                b[nf][0] = __float_as_uint(bs[(kk + ak    ) * BSTRIDE + c]);
                b[nf][1] = __float_as_uint(bs[(kk + ak + 4) * BSTRIDE + c]);
            }
#pragma unroll
            for (int mi = 0; mi < 4; mi++)
#pragma unroll
                for (int nf = 0; nf < 8; nf++) {
                    asm volatile(
                        "mma.sync.aligned.m16n8k8.row.col.f32.tf32.tf32.f32 "
                        "{%0,%1,%2,%3}, {%4,%5,%6,%7}, {%8,%9}, {%0,%1,%2,%3};"
                        : "+f"(acc[mi][nf][0]), "+f"(acc[mi][nf][1]),
                          "+f"(acc[mi][nf][2]), "+f"(acc[mi][nf][3])
                        : "r"(a[mi][0]), "r"(a[mi][1]), "r"(a[mi][2]), "r"(a[mi][3]),
                          "r"(b[nf][0]), "r"(b[nf][1]));
                }
        }
    }

    // epilogue
    const int gr = lane >> 2;
    const int gc = (lane & 3) * 2;
#pragma unroll
    for (int mi = 0; mi < 4; mi++) {
#pragma unroll
        for (int nf = 0; nf < 8; nf++) {
            const int col = bx * BN + n0 + nf * 8 + gc;
            const float b0 = bias[col], b1 = bias[col + 1];
            const int row0 = by * BM + m0 + mi * 16 + gr;

            float2 v0 = make_float2(acc[mi][nf][0] + b0, acc[mi][nf][1] + b1);
            float2 v1 = make_float2(acc[mi][nf][2] + b0, acc[mi][nf][3] + b1);
            if (relu) {
                v0.x = fmaxf(v0.x, 0.f); v0.y = fmaxf(v0.y, 0.f);
                v1.x = fmaxf(v1.x, 0.f); v1.y = fmaxf(v1.y, 0.f);
            }
            if (roundOut) {
                v0.x = rndt(v0.x); v0.y = rndt(v0.y);
                v1.x = rndt(v1.x); v1.y = rndt(v1.y);
            }
            *(float2*)(Cout + (size_t)row0 * N + col)       = v0;
            *(float2*)(Cout + (size_t)(row0 + 8) * N + col) = v1;
        }
    }
}

// ---------------- deformable sampling with fused softmax -------------------
__global__ void deform_kernel(const float* __restrict__ qkv,
                              const float* __restrict__ ref,
                              float* __restrict__ out) {
    const int q = blockIdx.x;
    const int h = threadIdx.x >> 5;
    const int d = threadIdx.x & 31;
    const int b = q / LQ_;

    const float* lg = qkv + (size_t)q * NQKV + 512 + h * 16;
    float w[16];
    float mx = -1e30f;
#pragma unroll
    for (int i = 0; i < 16; i++) { w[i] = lg[i]; mx = fmaxf(mx, w[i]); }
    float s = 0.f;
#pragma unroll
    for (int i = 0; i < 16; i++) { w[i] = __expf(w[i] - mx); s += w[i]; }
    const float inv = 1.f / s;

    const float rx = ref[(size_t)q * 2 + 0];
    const float ry = ref[(size_t)q * 2 + 1];
    const float* offq = qkv + (size_t)q * NQKV + 256 + h * 32;

    float acc = 0.f;
#pragma unroll
    for (int l = 0; l < 4; l++) {
        const int Hl = d_scH[l], Wl = d_scW[l], st = d_scSt[l];
        const float invW = 1.f / (float)Wl, invH = 1.f / (float)Hl;
        const float Wm1 = (float)(Wl - 1), Hm1 = (float)(Hl - 1);
        const float* vl = qkv + (size_t)(b * LQ_ + st) * NQKV + h * 32 + d;
#pragma unroll
        for (int k = 0; k < 4; k++) {
            const float ox = offq[l * 8 + k * 2 + 0];
            const float oy = offq[l * 8 + k * 2 + 1];
            const float ww = w[l * 4 + k] * inv;
            float x = (rx + ox * invW) * Wm1;
            float y = (ry + oy * invH) * Hm1;
            x = fminf(fmaxf(x, 0.f), Wm1);
            y = fminf(fmaxf(y, 0.f), Hm1);
            const float x0f = floorf(x), y0f = floorf(y);
            const int x0 = (int)x0f, y0 = (int)y0f;
            const int x1 = min(x0 + 1, Wl - 1), y1 = min(y0 + 1, Hl - 1);
            const float wx = x - x0f, wy = y - y0f;
            const float v00 = vl[(size_t)(y0 * Wl + x0) * NQKV];
            const float v01 = vl[(size_t)(y0 * Wl + x1) * NQKV];
            const float v10 = vl[(size_t)(y1 * Wl + x0) * NQKV];
            const float v11 = vl[(size_t)(y1 * Wl + x1) * NQKV];
            const float top = v00 + wx * (v01 - v00);
            const float bot = v10 + wx * (v11 - v10);
            acc = fmaf(ww, top + wy * (bot - top), acc);
        }
    }
    out[(size_t)q * C_ + h * 32 + d] = rndt(acc);
}

// ---------------- fused residual + layernorm (vectorized) ------------------
__global__ void ln_kernel(const float* __restrict__ a, const float* __restrict__ b,
                          const float* __restrict__ gamma, const float* __restrict__ beta,
                          const float* __restrict__ pos,
                          float* __restrict__ out, float* __restrict__ outT) {
    const int row = blockIdx.x * 8 + (threadIdx.x >> 5);
    const int lane = threadIdx.x & 31;
    const size_t base = (size_t)row * C_ + lane * 8;

    float vals[8];
    {
        float4 a0 = *(const float4*)(a + base);
        float4 a1 = *(const float4*)(a + base + 4);
        float4 b0 = *(const float4*)(b + base);
        float4 b1 = *(const float4*)(b + base + 4);
        vals[0] = a0.x + b0.x; vals[1] = a0.y + b0.y;
        vals[2] = a0.z + b0.z; vals[3] = a0.w + b0.w;
        vals[4] = a1.x + b1.x; vals[5] = a1.y + b1.y;
        vals[6] = a1.z + b1.z; vals[7] = a1.w + b1.w;
    }
    float s = 0.f;
#pragma unroll
    for (int i = 0; i < 8; i++) s += vals[i];
#pragma unroll
    for (int o = 16; o > 0; o >>= 1) s += __shfl_xor_sync(0xffffffffu, s, o);
    const float mean = s * (1.f / 256.f);
    float vs = 0.f;
#pragma unroll
    for (int i = 0; i < 8; i++) {
        const float dlt = vals[i] - mean;
        vs += dlt * dlt;
    }
#pragma unroll
    for (int o = 16; o > 0; o >>= 1) vs += __shfl_xor_sync(0xffffffffu, vs, o);
    const float rstd = rsqrtf(vs * (1.f / 256.f) + 1e-5f);

    const int c = lane * 8;
    float4 g0 = *(const float4*)(gamma + c);
    float4 g1 = *(const float4*)(gamma + c + 4);
    float4 t0 = *(const float4*)(beta + c);
    float4 t1 = *(const float4*)(beta + c + 4);
    float o[8];
    o[0] = (vals[0] - mean) * rstd * g0.x + t0.x;
    o[1] = (vals[1] - mean) * rstd * g0.y + t0.y;
    o[2] = (vals[2] - mean) * rstd * g0.z + t0.z;
    o[3] = (vals[3] - mean) * rstd * g0.w + t0.w;
    o[4] = (vals[4] - mean) * rstd * g1.x + t1.x;
    o[5] = (vals[5] - mean) * rstd * g1.y + t1.y;
    o[6] = (vals[6] - mean) * rstd * g1.z + t1.z;
    o[7] = (vals[7] - mean) * rstd * g1.w + t1.w;

    if (pos) {
        float4 p0 = *(const float4*)(pos + base);
        float4 p1 = *(const float4*)(pos + base + 4);
        o[0] += p0.x; o[1] += p0.y; o[2] += p0.z; o[3] += p0.w;
        o[4] += p1.x; o[5] += p1.y; o[6] += p1.z; o[7] += p1.w;
    }
    *(float4*)(out + base)     = make_float4(o[0], o[1], o[2], o[3]);
    *(float4*)(out + base + 4) = make_float4(o[4], o[5], o[6], o[7]);
    if (outT) {
        *(float4*)(outT + base)     = make_float4(rndt(o[0]), rndt(o[1]), rndt(o[2]), rndt(o[3]));
        *(float4*)(outT + base + 4) = make_float4(rndt(o[4]), rndt(o[5]), rndt(o[6]), rndt(o[7]));
    }
}

// ---------------- launch ----------------
extern "C" void kernel_launch(void* const* d_in, const int* in_sizes, int n_in,
                              void* d_out, int out_size) {
    const float* src  = (const float*)d_in[0];
    const float* pos  = (const float*)d_in[1];
    const float* ref  = (const float*)d_in[2];
    const float* Woff = (const float*)d_in[3];
    const float* boff = (const float*)d_in[4];
    const float* Wat  = (const float*)d_in[5];
    const float* bat  = (const float*)d_in[6];
    const float* Wv   = (const float*)d_in[7];
    const float* bv   = (const float*)d_in[8];
    const float* Wo   = (const float*)d_in[9];
    const float* bo   = (const float*)d_in[10];
    const float* W1   = (const float*)d_in[11];
    const float* b1   = (const float*)d_in[12];
    const float* W2   = (const float*)d_in[13];
    const float* b2   = (const float*)d_in[14];
    const float* n1s  = (const float*)d_in[15];
    const float* n1b  = (const float*)d_in[16];
    const float* n2s  = (const float*)d_in[17];
    const float* n2b  = (const float*)d_in[18];
    float* outp = (float*)d_out;

    float *xp, *xpT, *qkv, *samp, *a, *x, *xT, *hbuf, *fbuf;
    float *wq, *bq, *wo, *w1, *w2;
    cudaGetSymbolAddress((void**)&xp,   g_xp);
    cudaGetSymbolAddress((void**)&xpT,  g_xpT);
    cudaGetSymbolAddress((void**)&qkv,  g_qkv);
    cudaGetSymbolAddress((void**)&samp, g_samp);
    cudaGetSymbolAddress((void**)&a,    g_a);
    cudaGetSymbolAddress((void**)&x,    g_x);
    cudaGetSymbolAddress((void**)&xT,   g_xT);
    cudaGetSymbolAddress((void**)&hbuf, g_h);
    cudaGetSymbolAddress((void**)&fbuf, g_f);
    cudaGetSymbolAddress((void**)&wq,   g_wq);
    cudaGetSymbolAddress((void**)&bq,   g_bq);
    cudaGetSymbolAddress((void**)&wo,   g_wo);
    cudaGetSymbolAddress((void**)&w1,   g_w1);
    cudaGetSymbolAddress((void**)&w2,   g_w2);

    cudaFuncSetAttribute(tf32gemm_kernel,
                         cudaFuncAttributeMaxDynamicSharedMemorySize, GEMM_SMEM);

    // weight prep
    {
        const int nq = NL_ * C_ * NQKV;
        pack_qkv_kernel<<<(nq + 255) / 256, 256>>>(Wv, Woff, Wat, bv, boff, bat, wq, bq);
        const int n_wo = NL_ * C_ * C_ / 4;
        round_kernel<<<(n_wo + 255) / 256, 256>>>(Wo, wo, n_wo);
        const int n_w1 = NL_ * C_ * FF_ / 4;
        round_kernel<<<(n_w1 + 255) / 256, 256>>>(W1, w1, n_w1);
        const int n_w2 = NL_ * FF_ * C_ / 4;
        round_kernel<<<(n_w2 + 255) / 256, 256>>>(W2, w2, n_w2);
    }

    const int n4 = M_ * C_ / 4;
    const dim3 gQKV(NQKV / BN, M_ / BM);
    const dim3 gN256(2, M_ / BM);
    const dim3 gN1024(8, M_ / BM);

    add0_kernel<<<(n4 + 255) / 256, 256>>>(src, pos, xp, xpT, n4);

    for (int i = 0; i < NL_; i++) {
        tf32gemm_kernel<<<gQKV, 128, GEMM_SMEM>>>(xpT, wq + (size_t)i * C_ * NQKV,
                                                  bq + (size_t)i * NQKV, qkv, NQKV, C_, 0, 0);
        deform_kernel<<<M_, 256>>>(qkv, ref, samp);
        tf32gemm_kernel<<<gN256, 128, GEMM_SMEM>>>(samp, wo + (size_t)i * C_ * C_,
                                                   bo + (size_t)i * C_, a, 256, C_, 0, 0);
        ln_kernel<<<M_ / 8, 256>>>(xp, a, n1s + (size_t)i * C_, n1b + (size_t)i * C_,
                                   (const float*)nullptr, x, xT);
        tf32gemm_kernel<<<gN1024, 128, GEMM_SMEM>>>(xT, w1 + (size_t)i * C_ * FF_,
                                                    b1 + (size_t)i * FF_, hbuf, FF_, C_, 1, 1);
        tf32gemm_kernel<<<gN256, 128, GEMM_SMEM>>>(hbuf, w2 + (size_t)i * FF_ * C_,
                                                   b2 + (size_t)i * C_, fbuf, 256, FF_, 0, 0);
        if (i == NL_ - 1) {
            ln_kernel<<<M_ / 8, 256>>>(x, fbuf, n2s + (size_t)i * C_, n2b + (size_t)i * C_,
                                       (const float*)nullptr, outp, (float*)nullptr);
        } else {
            ln_kernel<<<M_ / 8, 256>>>(x, fbuf, n2s + (size_t)i * C_, n2b + (size_t)i * C_,
                                       pos, xp, xpT);
        }
    }
    (void)in_sizes; (void)n_in; (void)out_size;
}

// round 8
// speedup vs baseline: 1.0245x; 1.0073x over previous
#include <cuda_runtime.h>
#include <cuda_fp16.h>
#include <math.h>
#include <stdint.h>

// ---------------- problem constants ----------------
#define B_     2
#define LQ_    21760
#define M_     (B_ * LQ_)      // 43520
#define C_     256
#define NHEAD_ 8
#define NS_    4
#define NL_    6
#define FF_    1024
#define NQKV   640             // 256 (v) + 256 (off) + 128 (att logits)

__device__ __constant__ int d_scH[4]   = {128, 64, 32, 16};
__device__ __constant__ int d_scW[4]   = {128, 64, 32, 16};
__device__ __constant__ int d_scSt[4]  = {0, 16384, 20480, 21504};

// ---------------- scratch (device globals; no allocation) ----------------
__device__ float  g_xpT [(size_t)M_ * C_];    // tf32-rounded xp (A input + residual)
__device__ float  g_qkv [(size_t)M_ * NQKV];  // off|logits (v cols unused fp32)
__device__ __half g_vh  [(size_t)M_ * C_];    // fp16 value tensor for gather
__device__ float  g_samp[(size_t)M_ * C_];    // sampled value (tf32-rounded)
__device__ float  g_a   [(size_t)M_ * C_];    // attn out proj
__device__ float  g_x   [(size_t)M_ * C_];    // post-LN1 (tf32-rounded)
__device__ float  g_h   [(size_t)M_ * FF_];   // FFN hidden (tf32-rounded)
__device__ float  g_f   [(size_t)M_ * C_];    // FFN out
__device__ float  g_wq  [(size_t)NL_ * C_ * NQKV];
__device__ float  g_bq  [(size_t)NL_ * NQKV];
__device__ float  g_wo  [(size_t)NL_ * C_ * C_];
__device__ float  g_w1  [(size_t)NL_ * C_ * FF_];
__device__ float  g_w2  [(size_t)NL_ * FF_ * C_];

__device__ __forceinline__ uint32_t f2tf32(float x) {
    uint32_t r;
    asm("cvt.rna.tf32.f32 %0, %1;" : "=r"(r) : "f"(x));
    return r;
}
__device__ __forceinline__ float rndt(float x) { return __uint_as_float(f2tf32(x)); }

// ---------------- weight prep ----------------
__global__ void round_kernel(const float* __restrict__ src, float* __restrict__ dst, int n4) {
    int i = blockIdx.x * blockDim.x + threadIdx.x;
    if (i >= n4) return;
    float4 v = ((const float4*)src)[i];
    v.x = rndt(v.x); v.y = rndt(v.y); v.z = rndt(v.z); v.w = rndt(v.w);
    ((float4*)dst)[i] = v;
}

__global__ void pack_qkv_kernel(const float* __restrict__ Wv, const float* __restrict__ Woff,
                                const float* __restrict__ Wat,
                                const float* __restrict__ bv, const float* __restrict__ boff,
                                const float* __restrict__ bat,
                                float* __restrict__ wq, float* __restrict__ bq) {
    int idx = blockIdx.x * blockDim.x + threadIdx.x;
    const int total = NL_ * C_ * NQKV;
    if (idx < total) {
        const int c = idx % NQKV;
        const int k = (idx / NQKV) % C_;
        const int l = idx / (NQKV * C_);
        float v;
        if (c < 256)      v = Wv  [((size_t)l * C_ + k) * 256 + c];
        else if (c < 512) v = Woff[((size_t)l * C_ + k) * 256 + (c - 256)];
        else              v = Wat [((size_t)l * C_ + k) * 128 + (c - 512)];
        wq[idx] = rndt(v);
    }
    if (idx < NL_ * NQKV) {
        const int c = idx % NQKV;
        const int l = idx / NQKV;
        float v;
        if (c < 256)      v = bv  [l * 256 + c];
        else if (c < 512) v = boff[l * 256 + (c - 256)];
        else              v = bat [l * 128 + (c - 512)];
        bq[idx] = v;
    }
}

// ---------------- layer-0 prep: xpT = round(src + pos) ----------------
__global__ void add0_kernel(const float* __restrict__ a, const float* __restrict__ b,
                            float* __restrict__ outT, int n4) {
    int i = blockIdx.x * blockDim.x + threadIdx.x;
    if (i >= n4) return;
    float4 va = ((const float4*)a)[i];
    float4 vb = ((const float4*)b)[i];
    ((float4*)outT)[i] = make_float4(rndt(va.x + vb.x), rndt(va.y + vb.y),
                                     rndt(va.z + vb.z), rndt(va.w + vb.w));
}

// ---------------- tf32 GEMM: 128x128x32 tile, 128 threads, warp 64x64 ------
#define BM 128
#define BN 128
#define BK 32
#define ASTRIDE 36
#define BSTRIDE 136
#define ASZ (BM * ASTRIDE)
#define BSZ (BK * BSTRIDE)
#define STAGEF (ASZ + BSZ)
#define NSTAGE 3
#define GEMM_SMEM (NSTAGE * STAGEF * 4)   // 107520 B

__device__ __forceinline__ void cpa16(float* dst, const float* src) {
    uint32_t d = (uint32_t)__cvta_generic_to_shared(dst);
    asm volatile("cp.async.cg.shared.global [%0], [%1], 16;" :: "r"(d), "l"(src));
}

__global__ __launch_bounds__(128, 2)
void tf32gemm_kernel(const float* __restrict__ A, const float* __restrict__ W,
                     const float* __restrict__ bias, float* __restrict__ Cout,
                     __half* __restrict__ halfOut,
                     int N, int Kd, int relu, int roundOut) {
    extern __shared__ __align__(16) float sm[];

    const int tid  = threadIdx.x;
    const int warp = tid >> 5;
    const int lane = tid & 31;
    const int m0 = (warp >> 1) * 64;
    const int n0 = (warp & 1) * 64;
    const int bx = blockIdx.x, by = blockIdx.y;

    const int alr = tid >> 3;
    const int alc = (tid & 7) * 4;
    const int blr = tid >> 5;
    const int blc = (tid & 31) * 4;

    const float* Ag = A + (size_t)(by * BM) * Kd;
    const float* Wg = W + (size_t)bx * BN;

    float acc[4][8][4];
#pragma unroll
    for (int mi = 0; mi < 4; mi++)
#pragma unroll
        for (int nf = 0; nf < 8; nf++)
#pragma unroll
            for (int r = 0; r < 4; r++) acc[mi][nf][r] = 0.f;

    const int NK = Kd / BK;

#pragma unroll
    for (int s = 0; s < 2; s++) {
        if (s < NK) {
            float* as = sm + s * STAGEF;
            float* bs = as + ASZ;
            const int k0 = s * BK;
#pragma unroll
            for (int p = 0; p < 8; p++) {
                const int row = p * 16 + alr;
                cpa16(as + row * ASTRIDE + alc, Ag + (size_t)row * Kd + k0 + alc);
            }
#pragma unroll
            for (int p = 0; p < 8; p++) {
                const int row = p * 4 + blr;
                cpa16(bs + row * BSTRIDE + blc, Wg + (size_t)(k0 + row) * N + blc);
            }
            asm volatile("cp.async.commit_group;");
        }
    }

    const int ar = lane >> 2;
    const int ak = lane & 3;

    for (int i = 0; i < NK; i++) {
        asm volatile("cp.async.wait_group 1;");
        __syncthreads();

        if (i + 2 < NK) {
            const int k0 = (i + 2) * BK;
            float* as = sm + ((i + 2) % NSTAGE) * STAGEF;
            float* bs = as + ASZ;
#pragma unroll
            for (int p = 0; p < 8; p++) {
                const int row = p * 16 + alr;
                cpa16(as + row * ASTRIDE + alc, Ag + (size_t)row * Kd + k0 + alc);
            }
#pragma unroll
            for (int p = 0; p < 8; p++) {
                const int row = p * 4 + blr;
                cpa16(bs + row * BSTRIDE + blc, Wg + (size_t)(k0 + row) * N + blc);
            }
            asm volatile("cp.async.commit_group;");
        }

        const float* as = sm + (i % NSTAGE) * STAGEF;
        const float* bs = as + ASZ;

#pragma unroll
        for (int kk = 0; kk < BK; kk += 8) {
            uint32_t a[4][4];
            uint32_t b[8][2];
#pragma unroll
            for (int mi = 0; mi < 4; mi++) {
                const int r = m0 + mi * 16 + ar;
                a[mi][0] = __float_as_uint(as[(r    ) * ASTRIDE + kk + ak    ]);
                a[mi][1] = __float_as_uint(as[(r + 8) * ASTRIDE + kk + ak    ]);
                a[mi][2] = __float_as_uint(as[(r    ) * ASTRIDE + kk + ak + 4]);
                a[mi][3] = __float_as_uint(as[(r + 8) * ASTRIDE + kk + ak + 4]);
            }
#pragma unroll
            for (int nf = 0; nf < 8; nf++) {
                const int c = n0 + nf * 8 + ar;
                b[nf][0] = __float_as_uint(bs[(kk + ak    ) * BSTRIDE + c]);
                b[nf][1] = __float_as_uint(bs[(kk + ak + 4) * BSTRIDE + c]);
            }
#pragma unroll
            for (int mi = 0; mi < 4; mi++)
#pragma unroll
                for (int nf = 0; nf < 8; nf++) {
                    asm volatile(
                        "mma.sync.aligned.m16n8k8.row.col.f32.tf32.tf32.f32 "
                        "{%0,%1,%2,%3}, {%4,%5,%6,%7}, {%8,%9}, {%0,%1,%2,%3};"
                        : "+f"(acc[mi][nf][0]), "+f"(acc[mi][nf][1]),
                          "+f"(acc[mi][nf][2]), "+f"(acc[mi][nf][3])
                        : "r"(a[mi][0]), "r"(a[mi][1]), "r"(a[mi][2]), "r"(a[mi][3]),
                          "r"(b[nf][0]), "r"(b[nf][1]));
                }
        }
    }

    // epilogue
    const int gr = lane >> 2;
    const int gc = (lane & 3) * 2;
#pragma unroll
    for (int mi = 0; mi < 4; mi++) {
#pragma unroll
        for (int nf = 0; nf < 8; nf++) {
            const int col = bx * BN + n0 + nf * 8 + gc;
            const float b0 = bias[col], b1 = bias[col + 1];
            const int row0 = by * BM + m0 + mi * 16 + gr;

            float2 v0 = make_float2(acc[mi][nf][0] + b0, acc[mi][nf][1] + b1);
            float2 v1 = make_float2(acc[mi][nf][2] + b0, acc[mi][nf][3] + b1);
            if (relu) {
                v0.x = fmaxf(v0.x, 0.f); v0.y = fmaxf(v0.y, 0.f);
                v1.x = fmaxf(v1.x, 0.f); v1.y = fmaxf(v1.y, 0.f);
            }
            const bool vcols = (halfOut != nullptr) && (col < 256);
            if (vcols) {
                // v columns: emit fp16 for the gather; fp32 store skipped (unread)
                __half2 h0 = __floats2half2_rn(v0.x, v0.y);
                __half2 h1 = __floats2half2_rn(v1.x, v1.y);
                *(__half2*)(halfOut + (size_t)row0 * 256 + col)       = h0;
                *(__half2*)(halfOut + (size_t)(row0 + 8) * 256 + col) = h1;
            } else {
                if (roundOut) {
                    v0.x = rndt(v0.x); v0.y = rndt(v0.y);
                    v1.x = rndt(v1.x); v1.y = rndt(v1.y);
                }
                *(float2*)(Cout + (size_t)row0 * N + col)       = v0;
                *(float2*)(Cout + (size_t)(row0 + 8) * N + col) = v1;
            }
        }
    }
}

// ---------------- deformable sampling (fp16 v) with fused softmax ----------
__global__ void deform_kernel(const float* __restrict__ qkv,
                              const __half* __restrict__ vh,
                              const float* __restrict__ ref,
                              float* __restrict__ out) {
    const int q = blockIdx.x;
    const int h = threadIdx.x >> 5;
    const int d = threadIdx.x & 31;
    const int b = q / LQ_;

    const float* lg = qkv + (size_t)q * NQKV + 512 + h * 16;
    float w[16];
    float mx = -1e30f;
#pragma unroll
    for (int i = 0; i < 16; i++) { w[i] = lg[i]; mx = fmaxf(mx, w[i]); }
    float s = 0.f;
#pragma unroll
    for (int i = 0; i < 16; i++) { w[i] = __expf(w[i] - mx); s += w[i]; }
    const float inv = 1.f / s;

    const float rx = ref[(size_t)q * 2 + 0];
    const float ry = ref[(size_t)q * 2 + 1];
    const float* offq = qkv + (size_t)q * NQKV + 256 + h * 32;

    float acc = 0.f;
#pragma unroll
    for (int l = 0; l < 4; l++) {
        const int Hl = d_scH[l], Wl = d_scW[l], st = d_scSt[l];
        const float invW = 1.f / (float)Wl, invH = 1.f / (float)Hl;
        const float Wm1 = (float)(Wl - 1), Hm1 = (float)(Hl - 1);
        const __half* vl = vh + (size_t)(b * LQ_ + st) * 256 + h * 32 + d;
#pragma unroll
        for (int k = 0; k < 4; k++) {
            const float ox = offq[l * 8 + k * 2 + 0];
            const float oy = offq[l * 8 + k * 2 + 1];
            const float ww = w[l * 4 + k] * inv;
            float x = (rx + ox * invW) * Wm1;
            float y = (ry + oy * invH) * Hm1;
            x = fminf(fmaxf(x, 0.f), Wm1);
            y = fminf(fmaxf(y, 0.f), Hm1);
            const float x0f = floorf(x), y0f = floorf(y);
            const int x0 = (int)x0f, y0 = (int)y0f;
            const int x1 = min(x0 + 1, Wl - 1), y1 = min(y0 + 1, Hl - 1);
            const float wx = x - x0f, wy = y - y0f;
            const float v00 = __half2float(vl[(size_t)(y0 * Wl + x0) * 256]);
            const float v01 = __half2float(vl[(size_t)(y0 * Wl + x1) * 256]);
            const float v10 = __half2float(vl[(size_t)(y1 * Wl + x0) * 256]);
            const float v11 = __half2float(vl[(size_t)(y1 * Wl + x1) * 256]);
            const float top = v00 + wx * (v01 - v00);
            const float bot = v10 + wx * (v11 - v10);
            acc = fmaf(ww, top + wy * (bot - top), acc);
        }
    }
    out[(size_t)q * C_ + h * 32 + d] = rndt(acc);
}

// ---------------- fused residual + layernorm (single rounded output) -------
__global__ void ln_kernel(const float* __restrict__ a, const float* __restrict__ b,
                          const float* __restrict__ gamma, const float* __restrict__ beta,
                          const float* __restrict__ pos,
                          float* __restrict__ out, int roundOut) {
    const int row = blockIdx.x * 8 + (threadIdx.x >> 5);
    const int lane = threadIdx.x & 31;
    const size_t base = (size_t)row * C_ + lane * 8;

    float vals[8];
    {
        float4 a0 = *(const float4*)(a + base);
        float4 a1 = *(const float4*)(a + base + 4);
        float4 b0 = *(const float4*)(b + base);
        float4 b1 = *(const float4*)(b + base + 4);
        vals[0] = a0.x + b0.x; vals[1] = a0.y + b0.y;
        vals[2] = a0.z + b0.z; vals[3] = a0.w + b0.w;
        vals[4] = a1.x + b1.x; vals[5] = a1.y + b1.y;
        vals[6] = a1.z + b1.z; vals[7] = a1.w + b1.w;
    }
    float s = 0.f;
#pragma unroll
    for (int i = 0; i < 8; i++) s += vals[i];
#pragma unroll
    for (int o = 16; o > 0; o >>= 1) s += __shfl_xor_sync(0xffffffffu, s, o);
    const float mean = s * (1.f / 256.f);
    float vs = 0.f;
#pragma unroll
    for (int i = 0; i < 8; i++) {
        const float dlt = vals[i] - mean;
        vs += dlt * dlt;
    }
#pragma unroll
    for (int o = 16; o > 0; o >>= 1) vs += __shfl_xor_sync(0xffffffffu, vs, o);
    const float rstd = rsqrtf(vs * (1.f / 256.f) + 1e-5f);

    const int c = lane * 8;
    float4 g0 = *(const float4*)(gamma + c);
    float4 g1 = *(const float4*)(gamma + c + 4);
    float4 t0 = *(const float4*)(beta + c);
    float4 t1 = *(const float4*)(beta + c + 4);
    float o[8];
    o[0] = (vals[0] - mean) * rstd * g0.x + t0.x;
    o[1] = (vals[1] - mean) * rstd * g0.y + t0.y;
    o[2] = (vals[2] - mean) * rstd * g0.z + t0.z;
    o[3] = (vals[3] - mean) * rstd * g0.w + t0.w;
    o[4] = (vals[4] - mean) * rstd * g1.x + t1.x;
    o[5] = (vals[5] - mean) * rstd * g1.y + t1.y;
    o[6] = (vals[6] - mean) * rstd * g1.z + t1.z;
    o[7] = (vals[7] - mean) * rstd * g1.w + t1.w;

    if (pos) {
        float4 p0 = *(const float4*)(pos + base);
        float4 p1 = *(const float4*)(pos + base + 4);
        o[0] += p0.x; o[1] += p0.y; o[2] += p0.z; o[3] += p0.w;
        o[4] += p1.x; o[5] += p1.y; o[6] += p1.z; o[7] += p1.w;
    }
    if (roundOut) {
#pragma unroll
        for (int i = 0; i < 8; i++) o[i] = rndt(o[i]);
    }
    *(float4*)(out + base)     = make_float4(o[0], o[1], o[2], o[3]);
    *(float4*)(out + base + 4) = make_float4(o[4], o[5], o[6], o[7]);
}

// ---------------- launch ----------------
extern "C" void kernel_launch(void* const* d_in, const int* in_sizes, int n_in,
                              void* d_out, int out_size) {
    const float* src  = (const float*)d_in[0];
    const float* pos  = (const float*)d_in[1];
    const float* ref  = (const float*)d_in[2];
    const float* Woff = (const float*)d_in[3];
    const float* boff = (const float*)d_in[4];
    const float* Wat  = (const float*)d_in[5];
    const float* bat  = (const float*)d_in[6];
    const float* Wv   = (const float*)d_in[7];
    const float* bv   = (const float*)d_in[8];
    const float* Wo   = (const float*)d_in[9];
    const float* bo   = (const float*)d_in[10];
    const float* W1   = (const float*)d_in[11];
    const float* b1   = (const float*)d_in[12];
    const float* W2   = (const float*)d_in[13];
    const float* b2   = (const float*)d_in[14];
    const float* n1s  = (const float*)d_in[15];
    const float* n1b  = (const float*)d_in[16];
    const float* n2s  = (const float*)d_in[17];
    const float* n2b  = (const float*)d_in[18];
    float* outp = (float*)d_out;

    float *xpT, *qkv, *samp, *a, *x, *hbuf, *fbuf;
    float *wq, *bq, *wo, *w1, *w2;
    __half* vh;
    cudaGetSymbolAddress((void**)&xpT,  g_xpT);
    cudaGetSymbolAddress((void**)&qkv,  g_qkv);
    cudaGetSymbolAddress((void**)&vh,   g_vh);
    cudaGetSymbolAddress((void**)&samp, g_samp);
    cudaGetSymbolAddress((void**)&a,    g_a);
    cudaGetSymbolAddress((void**)&x,    g_x);
    cudaGetSymbolAddress((void**)&hbuf, g_h);
    cudaGetSymbolAddress((void**)&fbuf, g_f);
    cudaGetSymbolAddress((void**)&wq,   g_wq);
    cudaGetSymbolAddress((void**)&bq,   g_bq);
    cudaGetSymbolAddress((void**)&wo,   g_wo);
    cudaGetSymbolAddress((void**)&w1,   g_w1);
    cudaGetSymbolAddress((void**)&w2,   g_w2);

    cudaFuncSetAttribute(tf32gemm_kernel,
                         cudaFuncAttributeMaxDynamicSharedMemorySize, GEMM_SMEM);

    // weight prep
    {
        const int nq = NL_ * C_ * NQKV;
        pack_qkv_kernel<<<(nq + 255) / 256, 256>>>(Wv, Woff, Wat, bv, boff, bat, wq, bq);
        const int n_wo = NL_ * C_ * C_ / 4;
        round_kernel<<<(n_wo + 255) / 256, 256>>>(Wo, wo, n_wo);
        const int n_w1 = NL_ * C_ * FF_ / 4;
        round_kernel<<<(n_w1 + 255) / 256, 256>>>(W1, w1, n_w1);
        const int n_w2 = NL_ * FF_ * C_ / 4;
        round_kernel<<<(n_w2 + 255) / 256, 256>>>(W2, w2, n_w2);
    }

    const int n4 = M_ * C_ / 4;
    const dim3 gQKV(NQKV / BN, M_ / BM);
    const dim3 gN256(2, M_ / BM);
    const dim3 gN1024(8, M_ / BM);

    add0_kernel<<<(n4 + 255) / 256, 256>>>(src, pos, xpT, n4);

    for (int i = 0; i < NL_; i++) {
        // qkv: v cols → fp16 vh; off/logits → fp32 qkv
        tf32gemm_kernel<<<gQKV, 128, GEMM_SMEM>>>(xpT, wq + (size_t)i * C_ * NQKV,
                                                  bq + (size_t)i * NQKV, qkv, vh, NQKV, C_, 0, 0);
        deform_kernel<<<M_, 256>>>(qkv, vh, ref, samp);
        tf32gemm_kernel<<<gN256, 128, GEMM_SMEM>>>(samp, wo + (size_t)i * C_ * C_,
                                                   bo + (size_t)i * C_, a, (__half*)nullptr, 256, C_, 0, 0);
        // x = round(LN(xpT + a))
        ln_kernel<<<M_ / 8, 256>>>(xpT, a, n1s + (size_t)i * C_, n1b + (size_t)i * C_,
                                   (const float*)nullptr, x, 1);
        tf32gemm_kernel<<<gN1024, 128, GEMM_SMEM>>>(x, w1 + (size_t)i * C_ * FF_,
                                                    b1 + (size_t)i * FF_, hbuf, (__half*)nullptr, FF_, C_, 1, 1);
        tf32gemm_kernel<<<gN256, 128, GEMM_SMEM>>>(hbuf, w2 + (size_t)i * FF_ * C_,
                                                   b2 + (size_t)i * C_, fbuf, (__half*)nullptr, 256, FF_, 0, 0);
        if (i == NL_ - 1) {
            ln_kernel<<<M_ / 8, 256>>>(x, fbuf, n2s + (size_t)i * C_, n2b + (size_t)i * C_,
                                       (const float*)nullptr, outp, 0);
        } else {
            // xpT = round(LN(x + f) + pos)
            ln_kernel<<<M_ / 8, 256>>>(x, fbuf, n2s + (size_t)i * C_, n2b + (size_t)i * C_,
                                       pos, xpT, 1);
        }
    }
    (void)in_sizes; (void)n_in; (void)out_size;
}

// round 9
// speedup vs baseline: 1.2908x; 1.2599x over previous
#include <cuda_runtime.h>
#include <cuda_fp16.h>
#include <math.h>
#include <stdint.h>

// ---------------- problem constants ----------------
#define B_     2
#define LQ_    21760
#define M_     (B_ * LQ_)      // 43520
#define C_     256
#define NHEAD_ 8
#define NS_    4
#define NL_    6
#define FF_    1024
#define NQKV   640             // 256 (v) + 256 (off) + 128 (att logits)

__device__ __constant__ int d_scH[4]   = {128, 64, 32, 16};
__device__ __constant__ int d_scW[4]   = {128, 64, 32, 16};
__device__ __constant__ int d_scSt[4]  = {0, 16384, 20480, 21504};

// ---------------- scratch (device globals; no allocation) ----------------
__device__ float  g_xp  [(size_t)M_ * C_];    // x+pos exact (residual 1)
__device__ __half g_xpH [(size_t)M_ * C_];    // fp16 xp (GEMM A)
__device__ float  g_qkv [(size_t)M_ * NQKV];  // off|logits fp32
__device__ __half g_vh  [(size_t)M_ * C_];    // fp16 value tensor
__device__ __half g_sampH[(size_t)M_ * C_];   // sampled value fp16 (Wo input)
__device__ float  g_a   [(size_t)M_ * C_];    // attn out proj fp32
__device__ float  g_x   [(size_t)M_ * C_];    // post-LN1 exact (residual 2)
__device__ __half g_xH  [(size_t)M_ * C_];    // fp16 post-LN1 (W1 input)
__device__ __half g_hH  [(size_t)M_ * FF_];   // FFN hidden fp16 (W2 input)
__device__ float  g_f   [(size_t)M_ * C_];    // FFN out fp32
// fp16 weights
__device__ __half g_wq  [(size_t)NL_ * C_ * NQKV];
__device__ float  g_bq  [(size_t)NL_ * NQKV];
__device__ __half g_wo  [(size_t)NL_ * C_ * C_];
__device__ __half g_w1  [(size_t)NL_ * C_ * FF_];
__device__ __half g_w2  [(size_t)NL_ * FF_ * C_];

// ---------------- weight prep ----------------
__global__ void tohalf_kernel(const float* __restrict__ src, __half* __restrict__ dst, int n4) {
    int i = blockIdx.x * blockDim.x + threadIdx.x;
    if (i >= n4) return;
    float4 v = ((const float4*)src)[i];
    __half2 h0 = __floats2half2_rn(v.x, v.y);
    __half2 h1 = __floats2half2_rn(v.z, v.w);
    ((__half2*)dst)[i * 2]     = h0;
    ((__half2*)dst)[i * 2 + 1] = h1;
}

__global__ void pack_qkv_kernel(const float* __restrict__ Wv, const float* __restrict__ Woff,
                                const float* __restrict__ Wat,
                                const float* __restrict__ bv, const float* __restrict__ boff,
                                const float* __restrict__ bat,
                                __half* __restrict__ wq, float* __restrict__ bq) {
    int idx = blockIdx.x * blockDim.x + threadIdx.x;
    const int total = NL_ * C_ * NQKV;
    if (idx < total) {
        const int c = idx % NQKV;
        const int k = (idx / NQKV) % C_;
        const int l = idx / (NQKV * C_);
        float v;
        if (c < 256)      v = Wv  [((size_t)l * C_ + k) * 256 + c];
        else if (c < 512) v = Woff[((size_t)l * C_ + k) * 256 + (c - 256)];
        else              v = Wat [((size_t)l * C_ + k) * 128 + (c - 512)];
        wq[idx] = __float2half(v);
    }
    if (idx < NL_ * NQKV) {
        const int c = idx % NQKV;
        const int l = idx / NQKV;
        float v;
        if (c < 256)      v = bv  [l * 256 + c];
        else if (c < 512) v = boff[l * 256 + (c - 256)];
        else              v = bat [l * 128 + (c - 512)];
        bq[idx] = v;
    }
}

// ---------------- layer-0 prep: xp = src + pos (fp32 + fp16) ----------------
__global__ void add0_kernel(const float* __restrict__ a, const float* __restrict__ b,
                            float* __restrict__ out, __half* __restrict__ outH, int n4) {
    int i = blockIdx.x * blockDim.x + threadIdx.x;
    if (i >= n4) return;
    float4 va = ((const float4*)a)[i];
    float4 vb = ((const float4*)b)[i];
    va.x += vb.x; va.y += vb.y; va.z += vb.z; va.w += vb.w;
    ((float4*)out)[i] = va;
    ((__half2*)outH)[i * 2]     = __floats2half2_rn(va.x, va.y);
    ((__half2*)outH)[i * 2 + 1] = __floats2half2_rn(va.z, va.w);
}

// ---------------- fp16 tensor-core GEMM (m16n8k16), cp.async 3-stage -------
// 128x128x32 tile, 128 threads (2x2 warps, 64x64 each), ldmatrix fragments.
#define BM 128
#define BN 128
#define BK 32
#define ASTR 40     // halves per A row (32 + 8 pad) — LDSM conflict-free
#define BSTR 136    // halves per B row (128 + 8 pad)
#define ASZ_H (BM * ASTR)          // 5120 halves
#define BSZ_H (BK * BSTR)          // 4352 halves
#define STAGE_H (ASZ_H + BSZ_H)    // 9472 halves = 18944 B
#define NSTAGE 3
#define GEMM_SMEM (NSTAGE * STAGE_H * 2)   // 56832 B

__device__ __forceinline__ void cpa16h(__half* dst, const __half* src) {
    uint32_t d = (uint32_t)__cvta_generic_to_shared(dst);
    asm volatile("cp.async.cg.shared.global [%0], [%1], 16;" :: "r"(d), "l"(src));
}
__device__ __forceinline__ uint32_t s2u(const __half* p) {
    return (uint32_t)__cvta_generic_to_shared(p);
}

// mode: 0 = fp32 out; 1 = fp16 out; 2 = qkv split (col<256 -> fp16 vh, else fp32)
__global__ __launch_bounds__(128, 2)
void h16gemm_kernel(const __half* __restrict__ A, const __half* __restrict__ W,
                    const float* __restrict__ bias, float* __restrict__ Cout,
                    __half* __restrict__ Hout,
                    int N, int Kd, int relu, int mode) {
    extern __shared__ __align__(16) __half smh[];

    const int tid  = threadIdx.x;
    const int warp = tid >> 5;
    const int lane = tid & 31;
    const int m0 = (warp >> 1) * 64;
    const int n0 = (warp & 1) * 64;
    const int bx = blockIdx.x, by = blockIdx.y;

    // loaders: A row = 32 halves = 4x16B chunks; B row = 128 halves = 16 chunks
    const int alr = tid >> 2;            // 0..31
    const int alc = (tid & 3) * 8;       // halves
    const int blr = tid >> 4;            // 0..7
    const int blc = (tid & 15) * 8;      // halves

    const __half* Ag = A + (size_t)(by * BM) * Kd;
    const __half* Wg = W + (size_t)bx * BN;

    float acc[4][8][4];
#pragma unroll
    for (int mi = 0; mi < 4; mi++)
#pragma unroll
        for (int nf = 0; nf < 8; nf++)
#pragma unroll
            for (int r = 0; r < 4; r++) acc[mi][nf][r] = 0.f;

    const int NK = Kd / BK;

#pragma unroll
    for (int s = 0; s < 2; s++) {
        if (s < NK) {
            __half* as = smh + s * STAGE_H;
            __half* bs = as + ASZ_H;
            const int k0 = s * BK;
#pragma unroll
            for (int p = 0; p < 4; p++) {
                const int row = p * 32 + alr;
                cpa16h(as + row * ASTR + alc, Ag + (size_t)row * Kd + k0 + alc);
            }
#pragma unroll
            for (int p = 0; p < 4; p++) {
                const int row = p * 8 + blr;
                cpa16h(bs + row * BSTR + blc, Wg + (size_t)(k0 + row) * N + blc);
            }
            asm volatile("cp.async.commit_group;");
        }
    }

    // ldmatrix lane roles
    const int amat = lane >> 3;          // 0..3
    const int arow = lane & 7;
    const int bl   = lane & 15;
    const int bmat = bl >> 3;            // 0..1
    const int brow = bl & 7;

    for (int i = 0; i < NK; i++) {
        asm volatile("cp.async.wait_group 1;");
        __syncthreads();

        if (i + 2 < NK) {
            const int k0 = (i + 2) * BK;
            __half* as = smh + ((i + 2) % NSTAGE) * STAGE_H;
            __half* bs = as + ASZ_H;
#pragma unroll
            for (int p = 0; p < 4; p++) {
                const int row = p * 32 + alr;
                cpa16h(as + row * ASTR + alc, Ag + (size_t)row * Kd + k0 + alc);
            }
#pragma unroll
            for (int p = 0; p < 4; p++) {
                const int row = p * 8 + blr;
                cpa16h(bs + row * BSTR + blc, Wg + (size_t)(k0 + row) * N + blc);
            }
            asm volatile("cp.async.commit_group;");
        }

        const __half* as = smh + (i % NSTAGE) * STAGE_H;
        const __half* bs = as + ASZ_H;

#pragma unroll
        for (int kk = 0; kk < BK; kk += 16) {
            uint32_t a[4][4], b[8][2];
#pragma unroll
            for (int mi = 0; mi < 4; mi++) {
                const int r = m0 + mi * 16 + (amat & 1) * 8 + arow;
                const int c = kk + (amat >> 1) * 8;
                const uint32_t addr = s2u(as + r * ASTR + c);
                asm volatile("ldmatrix.sync.aligned.m8n8.x4.shared.b16 {%0,%1,%2,%3}, [%4];"
                             : "=r"(a[mi][0]), "=r"(a[mi][1]), "=r"(a[mi][2]), "=r"(a[mi][3])
                             : "r"(addr));
            }
#pragma unroll
            for (int nf = 0; nf < 8; nf++) {
                const int r = kk + bmat * 8 + brow;
                const int c = n0 + nf * 8;
                const uint32_t addr = s2u(bs + r * BSTR + c);
                asm volatile("ldmatrix.sync.aligned.m8n8.x2.trans.shared.b16 {%0,%1}, [%2];"
                             : "=r"(b[nf][0]), "=r"(b[nf][1]) : "r"(addr));
            }
#pragma unroll
            for (int mi = 0; mi < 4; mi++)
#pragma unroll
                for (int nf = 0; nf < 8; nf++) {
                    asm volatile(
                        "mma.sync.aligned.m16n8k16.row.col.f32.f16.f16.f32 "
                        "{%0,%1,%2,%3}, {%4,%5,%6,%7}, {%8,%9}, {%0,%1,%2,%3};"
                        : "+f"(acc[mi][nf][0]), "+f"(acc[mi][nf][1]),
                          "+f"(acc[mi][nf][2]), "+f"(acc[mi][nf][3])
                        : "r"(a[mi][0]), "r"(a[mi][1]), "r"(a[mi][2]), "r"(a[mi][3]),
                          "r"(b[nf][0]), "r"(b[nf][1]));
                }
        }
    }

    // epilogue: bias (+relu), fp32 / fp16 / split stores
    const int gr = lane >> 2;
    const int gc = (lane & 3) * 2;
#pragma unroll
    for (int mi = 0; mi < 4; mi++) {
#pragma unroll
        for (int nf = 0; nf < 8; nf++) {
            const int col = bx * BN + n0 + nf * 8 + gc;
            const float b0 = bias[col], b1 = bias[col + 1];
            const int row0 = by * BM + m0 + mi * 16 + gr;

            float2 v0 = make_float2(acc[mi][nf][0] + b0, acc[mi][nf][1] + b1);
            float2 v1 = make_float2(acc[mi][nf][2] + b0, acc[mi][nf][3] + b1);
            if (relu) {
                v0.x = fmaxf(v0.x, 0.f); v0.y = fmaxf(v0.y, 0.f);
                v1.x = fmaxf(v1.x, 0.f); v1.y = fmaxf(v1.y, 0.f);
            }
            if (mode == 1 || (mode == 2 && col < 256)) {
                const int hstride = (mode == 2) ? 256 : N;
                *(__half2*)(Hout + (size_t)row0 * hstride + col)       = __floats2half2_rn(v0.x, v0.y);
                *(__half2*)(Hout + (size_t)(row0 + 8) * hstride + col) = __floats2half2_rn(v1.x, v1.y);
            } else {
                *(float2*)(Cout + (size_t)row0 * N + col)       = v0;
                *(float2*)(Cout + (size_t)(row0 + 8) * N + col) = v1;
            }
        }
    }
}

// ---------------- deformable sampling (fp16 v) with fused softmax ----------
__global__ void deform_kernel(const float* __restrict__ qkv,
                              const __half* __restrict__ vh,
                              const float* __restrict__ ref,
                              __half* __restrict__ out) {
    const int q = blockIdx.x;
    const int h = threadIdx.x >> 5;
    const int d = threadIdx.x & 31;
    const int b = q / LQ_;

    const float* lg = qkv + (size_t)q * NQKV + 512 + h * 16;
    float w[16];
    float mx = -1e30f;
#pragma unroll
    for (int i = 0; i < 16; i++) { w[i] = lg[i]; mx = fmaxf(mx, w[i]); }
    float s = 0.f;
#pragma unroll
    for (int i = 0; i < 16; i++) { w[i] = __expf(w[i] - mx); s += w[i]; }
    const float inv = 1.f / s;

    const float rx = ref[(size_t)q * 2 + 0];
    const float ry = ref[(size_t)q * 2 + 1];
    const float* offq = qkv + (size_t)q * NQKV + 256 + h * 32;

    float acc = 0.f;
#pragma unroll
    for (int l = 0; l < 4; l++) {
        const int Hl = d_scH[l], Wl = d_scW[l], st = d_scSt[l];
        const float invW = 1.f / (float)Wl, invH = 1.f / (float)Hl;
        const float Wm1 = (float)(Wl - 1), Hm1 = (float)(Hl - 1);
        const __half* vl = vh + (size_t)(b * LQ_ + st) * 256 + h * 32 + d;
#pragma unroll
        for (int k = 0; k < 4; k++) {
            const float ox = offq[l * 8 + k * 2 + 0];
            const float oy = offq[l * 8 + k * 2 + 1];
            const float ww = w[l * 4 + k] * inv;
            float x = (rx + ox * invW) * Wm1;
            float y = (ry + oy * invH) * Hm1;
            x = fminf(fmaxf(x, 0.f), Wm1);
            y = fminf(fmaxf(y, 0.f), Hm1);
            const float x0f = floorf(x), y0f = floorf(y);
            const int x0 = (int)x0f, y0 = (int)y0f;
            const int x1 = min(x0 + 1, Wl - 1), y1 = min(y0 + 1, Hl - 1);
            const float wx = x - x0f, wy = y - y0f;
            const float v00 = __half2float(vl[(size_t)(y0 * Wl + x0) * 256]);
            const float v01 = __half2float(vl[(size_t)(y0 * Wl + x1) * 256]);
            const float v10 = __half2float(vl[(size_t)(y1 * Wl + x0) * 256]);
            const float v11 = __half2float(vl[(size_t)(y1 * Wl + x1) * 256]);
            const float top = v00 + wx * (v01 - v00);
            const float bot = v10 + wx * (v11 - v10);
            acc = fmaf(ww, top + wy * (bot - top), acc);
        }
    }
    out[(size_t)q * C_ + h * 32 + d] = __float2half(acc);
}

// ---------------- fused residual + layernorm (fp32 + optional fp16) --------
__global__ void ln_kernel(const float* __restrict__ a, const float* __restrict__ b,
                          const float* __restrict__ gamma, const float* __restrict__ beta,
                          const float* __restrict__ pos,
                          float* __restrict__ out, __half* __restrict__ outH) {
    const int row = blockIdx.x * 8 + (threadIdx.x >> 5);
    const int lane = threadIdx.x & 31;
    const size_t base = (size_t)row * C_ + lane * 8;

    float vals[8];
    {
        float4 a0 = *(const float4*)(a + base);
        float4 a1 = *(const float4*)(a + base + 4);
        float4 b0 = *(const float4*)(b + base);
        float4 b1 = *(const float4*)(b + base + 4);
        vals[0] = a0.x + b0.x; vals[1] = a0.y + b0.y;
        vals[2] = a0.z + b0.z; vals[3] = a0.w + b0.w;
        vals[4] = a1.x + b1.x; vals[5] = a1.y + b1.y;
        vals[6] = a1.z + b1.z; vals[7] = a1.w + b1.w;
    }
    float s = 0.f;
#pragma unroll
    for (int i = 0; i < 8; i++) s += vals[i];
#pragma unroll
    for (int o = 16; o > 0; o >>= 1) s += __shfl_xor_sync(0xffffffffu, s, o);
    const float mean = s * (1.f / 256.f);
    float vs = 0.f;
#pragma unroll
    for (int i = 0; i < 8; i++) {
        const float dlt = vals[i] - mean;
        vs += dlt * dlt;
    }
#pragma unroll
    for (int o = 16; o > 0; o >>= 1) vs += __shfl_xor_sync(0xffffffffu, vs, o);
    const float rstd = rsqrtf(vs * (1.f / 256.f) + 1e-5f);

    const int c = lane * 8;
    float4 g0 = *(const float4*)(gamma + c);
    float4 g1 = *(const float4*)(gamma + c + 4);
    float4 t0 = *(const float4*)(beta + c);
    float4 t1 = *(const float4*)(beta + c + 4);
    float o[8];
    o[0] = (vals[0] - mean) * rstd * g0.x + t0.x;
    o[1] = (vals[1] - mean) * rstd * g0.y + t0.y;
    o[2] = (vals[2] - mean) * rstd * g0.z + t0.z;
    o[3] = (vals[3] - mean) * rstd * g0.w + t0.w;
    o[4] = (vals[4] - mean) * rstd * g1.x + t1.x;
    o[5] = (vals[5] - mean) * rstd * g1.y + t1.y;
    o[6] = (vals[6] - mean) * rstd * g1.z + t1.z;
    o[7] = (vals[7] - mean) * rstd * g1.w + t1.w;

    if (pos) {
        float4 p0 = *(const float4*)(pos + base);
        float4 p1 = *(const float4*)(pos + base + 4);
        o[0] += p0.x; o[1] += p0.y; o[2] += p0.z; o[3] += p0.w;
        o[4] += p1.x; o[5] += p1.y; o[6] += p1.z; o[7] += p1.w;
    }
    *(float4*)(out + base)     = make_float4(o[0], o[1], o[2], o[3]);
    *(float4*)(out + base + 4) = make_float4(o[4], o[5], o[6], o[7]);
    if (outH) {
        *(__half2*)(outH + base)     = __floats2half2_rn(o[0], o[1]);
        *(__half2*)(outH + base + 2) = __floats2half2_rn(o[2], o[3]);
        *(__half2*)(outH + base + 4) = __floats2half2_rn(o[4], o[5]);
        *(__half2*)(outH + base + 6) = __floats2half2_rn(o[6], o[7]);
    }
}

// ---------------- launch ----------------
extern "C" void kernel_launch(void* const* d_in, const int* in_sizes, int n_in,
                              void* d_out, int out_size) {
    const float* src  = (const float*)d_in[0];
    const float* pos  = (const float*)d_in[1];
    const float* ref  = (const float*)d_in[2];
    const float* Woff = (const float*)d_in[3];
    const float* boff = (const float*)d_in[4];
    const float* Wat  = (const float*)d_in[5];
    const float* bat  = (const float*)d_in[6];
    const float* Wv   = (const float*)d_in[7];
    const float* bv   = (const float*)d_in[8];
    const float* Wo   = (const float*)d_in[9];
    const float* bo   = (const float*)d_in[10];
    const float* W1   = (const float*)d_in[11];
    const float* b1   = (const float*)d_in[12];
    const float* W2   = (const float*)d_in[13];
    const float* b2   = (const float*)d_in[14];
    const float* n1s  = (const float*)d_in[15];
    const float* n1b  = (const float*)d_in[16];
    const float* n2s  = (const float*)d_in[17];
    const float* n2b  = (const float*)d_in[18];
    float* outp = (float*)d_out;

    float *xp, *qkv, *a, *x, *fbuf, *bq;
    __half *xpH, *vh, *sampH, *xH, *hH, *wq, *wo, *w1, *w2;
    cudaGetSymbolAddress((void**)&xp,    g_xp);
    cudaGetSymbolAddress((void**)&xpH,   g_xpH);
    cudaGetSymbolAddress((void**)&qkv,   g_qkv);
    cudaGetSymbolAddress((void**)&vh,    g_vh);
    cudaGetSymbolAddress((void**)&sampH, g_sampH);
    cudaGetSymbolAddress((void**)&a,     g_a);
    cudaGetSymbolAddress((void**)&x,     g_x);
    cudaGetSymbolAddress((void**)&xH,    g_xH);
    cudaGetSymbolAddress((void**)&hH,    g_hH);
    cudaGetSymbolAddress((void**)&fbuf,  g_f);
    cudaGetSymbolAddress((void**)&wq,    g_wq);
    cudaGetSymbolAddress((void**)&bq,    g_bq);
    cudaGetSymbolAddress((void**)&wo,    g_wo);
    cudaGetSymbolAddress((void**)&w1,    g_w1);
    cudaGetSymbolAddress((void**)&w2,    g_w2);

    cudaFuncSetAttribute(h16gemm_kernel,
                         cudaFuncAttributeMaxDynamicSharedMemorySize, GEMM_SMEM);

    // weight prep
    {
        const int nq = NL_ * C_ * NQKV;
        pack_qkv_kernel<<<(nq + 255) / 256, 256>>>(Wv, Woff, Wat, bv, boff, bat, wq, bq);
        const int n_wo = NL_ * C_ * C_ / 4;
        tohalf_kernel<<<(n_wo + 255) / 256, 256>>>(Wo, wo, n_wo);
        const int n_w1 = NL_ * C_ * FF_ / 4;
        tohalf_kernel<<<(n_w1 + 255) / 256, 256>>>(W1, w1, n_w1);
        const int n_w2 = NL_ * FF_ * C_ / 4;
        tohalf_kernel<<<(n_w2 + 255) / 256, 256>>>(W2, w2, n_w2);
    }

    const int n4 = M_ * C_ / 4;
    const dim3 gQKV(NQKV / BN, M_ / BM);
    const dim3 gN256(2, M_ / BM);
    const dim3 gN1024(8, M_ / BM);

    add0_kernel<<<(n4 + 255) / 256, 256>>>(src, pos, xp, xpH, n4);

    for (int i = 0; i < NL_; i++) {
        // qkv: v cols -> fp16 vh; off/logits -> fp32 qkv
        h16gemm_kernel<<<gQKV, 128, GEMM_SMEM>>>(xpH, wq + (size_t)i * C_ * NQKV,
                                                 bq + (size_t)i * NQKV, qkv, vh, NQKV, C_, 0, 2);
        deform_kernel<<<M_, 256>>>(qkv, vh, ref, sampH);
        // a = samp @ Wo + bo (fp32)
        h16gemm_kernel<<<gN256, 128, GEMM_SMEM>>>(sampH, wo + (size_t)i * C_ * C_,
                                                  bo + (size_t)i * C_, a, (__half*)nullptr, 256, C_, 0, 0);
        // x = LN(xp + a) -> fp32 x + fp16 xH
        ln_kernel<<<M_ / 8, 256>>>(xp, a, n1s + (size_t)i * C_, n1b + (size_t)i * C_,
                                   (const float*)nullptr, x, xH);
        // h = relu(x @ W1 + b1) -> fp16
        h16gemm_kernel<<<gN1024, 128, GEMM_SMEM>>>(xH, w1 + (size_t)i * C_ * FF_,
                                                   b1 + (size_t)i * FF_, (float*)nullptr, hH, FF_, C_, 1, 1);
        // f = h @ W2 + b2 (fp32)
        h16gemm_kernel<<<gN256, 128, GEMM_SMEM>>>(hH, w2 + (size_t)i * FF_ * C_,
                                                  b2 + (size_t)i * C_, fbuf, (__half*)nullptr, 256, FF_, 0, 0);
        if (i == NL_ - 1) {
            ln_kernel<<<M_ / 8, 256>>>(x, fbuf, n2s + (size_t)i * C_, n2b + (size_t)i * C_,
                                       (const float*)nullptr, outp, (__half*)nullptr);
        } else {
            // xp = LN(x + f) + pos (fp32) ; xpH = fp16(xp)
            ln_kernel<<<M_ / 8, 256>>>(x, fbuf, n2s + (size_t)i * C_, n2b + (size_t)i * C_,
                                       pos, xp, xpH);
        }
    }
    (void)in_sizes; (void)n_in; (void)out_size;
}

// round 11
// speedup vs baseline: 1.8874x; 1.4622x over previous
#include <cuda_runtime.h>
#include <cuda_fp16.h>
#include <math.h>
#include <stdint.h>

// ---------------- problem constants ----------------
#define B_     2
#define LQ_    21760
#define M_     (B_ * LQ_)      // 43520
#define C_     256
#define NHEAD_ 8
#define NS_    4
#define NL_    6
#define FF_    1024
#define NQKV   640             // 256 (v) + 256 (off) + 128 (att logits)

__device__ __constant__ int d_scH[4]   = {128, 64, 32, 16};
__device__ __constant__ int d_scW[4]   = {128, 64, 32, 16};
__device__ __constant__ int d_scSt[4]  = {0, 16384, 20480, 21504};

// ---------------- scratch (device globals; no allocation) ----------------
__device__ float  g_xp  [(size_t)M_ * C_];    // x+pos exact (residual 1)
__device__ __half g_xpH [(size_t)M_ * C_];    // fp16 xp (GEMM A)
__device__ float  g_qkv [(size_t)M_ * NQKV];  // off|logits fp32
__device__ __half g_vh  [(size_t)M_ * C_];    // fp16 value tensor
__device__ __half g_sampH[(size_t)M_ * C_];   // sampled value fp16 (Wo input)
__device__ float  g_a   [(size_t)M_ * C_];    // attn out proj fp32
__device__ float  g_x   [(size_t)M_ * C_];    // post-LN1 exact (residual 2)
__device__ __half g_xH  [(size_t)M_ * C_];    // fp16 post-LN1 (W1 input)
__device__ __half g_hH  [(size_t)M_ * FF_];   // FFN hidden fp16 (W2 input)
__device__ float  g_f   [(size_t)M_ * C_];    // FFN out fp32
// fp16 weights
__device__ __half g_wq  [(size_t)NL_ * C_ * NQKV];
__device__ float  g_bq  [(size_t)NL_ * NQKV];
__device__ __half g_wo  [(size_t)NL_ * C_ * C_];
__device__ __half g_w1  [(size_t)NL_ * C_ * FF_];
__device__ __half g_w2  [(size_t)NL_ * FF_ * C_];

// ---------------- weight prep ----------------
__global__ void tohalf_kernel(const float* __restrict__ src, __half* __restrict__ dst, int n4) {
    int i = blockIdx.x * blockDim.x + threadIdx.x;
    if (i >= n4) return;
    float4 v = ((const float4*)src)[i];
    __half2 h0 = __floats2half2_rn(v.x, v.y);
    __half2 h1 = __floats2half2_rn(v.z, v.w);
    ((__half2*)dst)[i * 2]     = h0;
    ((__half2*)dst)[i * 2 + 1] = h1;
}

__global__ void pack_qkv_kernel(const float* __restrict__ Wv, const float* __restrict__ Woff,
                                const float* __restrict__ Wat,
                                const float* __restrict__ bv, const float* __restrict__ boff,
                                const float* __restrict__ bat,
                                __half* __restrict__ wq, float* __restrict__ bq) {
    int idx = blockIdx.x * blockDim.x + threadIdx.x;
    const int total = NL_ * C_ * NQKV;
    if (idx < total) {
        const int c = idx % NQKV;
        const int k = (idx / NQKV) % C_;
        const int l = idx / (NQKV * C_);
        float v;
        if (c < 256)      v = Wv  [((size_t)l * C_ + k) * 256 + c];
        else if (c < 512) v = Woff[((size_t)l * C_ + k) * 256 + (c - 256)];
        else              v = Wat [((size_t)l * C_ + k) * 128 + (c - 512)];
        wq[idx] = __float2half(v);
    }
    if (idx < NL_ * NQKV) {
        const int c = idx % NQKV;
        const int l = idx / NQKV;
        float v;
        if (c < 256)      v = bv  [l * 256 + c];
        else if (c < 512) v = boff[l * 256 + (c - 256)];
        else              v = bat [l * 128 + (c - 512)];
        bq[idx] = v;
    }
}

// ---------------- layer-0 prep: xp = src + pos (fp32 + fp16) ----------------
__global__ void add0_kernel(const float* __restrict__ a, const float* __restrict__ b,
                            float* __restrict__ out, __half* __restrict__ outH, int n4) {
    int i = blockIdx.x * blockDim.x + threadIdx.x;
    if (i >= n4) return;
    float4 va = ((const float4*)a)[i];
    float4 vb = ((const float4*)b)[i];
    va.x += vb.x; va.y += vb.y; va.z += vb.z; va.w += vb.w;
    ((float4*)out)[i] = va;
    ((__half2*)outH)[i * 2]     = __floats2half2_rn(va.x, va.y);
    ((__half2*)outH)[i * 2 + 1] = __floats2half2_rn(va.z, va.w);
}

// ---------------- fp16 tensor-core GEMM (m16n8k16), cp.async 3-stage -------
#define BM 128
#define BN 128
#define BK 32
#define ASTR 40
#define BSTR 136
#define ASZ_H (BM * ASTR)
#define BSZ_H (BK * BSTR)
#define STAGE_H (ASZ_H + BSZ_H)
#define NSTAGE 3
#define GEMM_SMEM (NSTAGE * STAGE_H * 2)   // 56832 B

__device__ __forceinline__ void cpa16h(__half* dst, const __half* src) {
    uint32_t d = (uint32_t)__cvta_generic_to_shared(dst);
    asm volatile("cp.async.cg.shared.global [%0], [%1], 16;" :: "r"(d), "l"(src));
}
__device__ __forceinline__ uint32_t s2u(const __half* p) {
    return (uint32_t)__cvta_generic_to_shared(p);
}

// mode: 0 = fp32 out; 1 = fp16 out; 2 = qkv split (col<256 -> fp16 vh, else fp32)
__global__ __launch_bounds__(128, 2)
void h16gemm_kernel(const __half* __restrict__ A, const __half* __restrict__ W,
                    const float* __restrict__ bias, float* __restrict__ Cout,
                    __half* __restrict__ Hout,
                    int N, int Kd, int relu, int mode) {
    extern __shared__ __align__(16) __half smh[];

    const int tid  = threadIdx.x;
    const int warp = tid >> 5;
    const int lane = tid & 31;
    const int m0 = (warp >> 1) * 64;
    const int n0 = (warp & 1) * 64;
    const int bx = blockIdx.x, by = blockIdx.y;

    const int alr = tid >> 2;
    const int alc = (tid & 3) * 8;
    const int blr = tid >> 4;
    const int blc = (tid & 15) * 8;

    const __half* Ag = A + (size_t)(by * BM) * Kd;
    const __half* Wg = W + (size_t)bx * BN;

    float acc[4][8][4];
#pragma unroll
    for (int mi = 0; mi < 4; mi++)
#pragma unroll
        for (int nf = 0; nf < 8; nf++)
#pragma unroll
            for (int r = 0; r < 4; r++) acc[mi][nf][r] = 0.f;

    const int NK = Kd / BK;

#pragma unroll
    for (int s = 0; s < 2; s++) {
        if (s < NK) {
            __half* as = smh + s * STAGE_H;
            __half* bs = as + ASZ_H;
            const int k0 = s * BK;
#pragma unroll
            for (int p = 0; p < 4; p++) {
                const int row = p * 32 + alr;
                cpa16h(as + row * ASTR + alc, Ag + (size_t)row * Kd + k0 + alc);
            }
#pragma unroll
            for (int p = 0; p < 4; p++) {
                const int row = p * 8 + blr;
                cpa16h(bs + row * BSTR + blc, Wg + (size_t)(k0 + row) * N + blc);
            }
            asm volatile("cp.async.commit_group;");
        }
    }

    const int amat = lane >> 3;
    const int arow = lane & 7;
    const int bl   = lane & 15;
    const int bmat = bl >> 3;
    const int brow = bl & 7;

    for (int i = 0; i < NK; i++) {
        asm volatile("cp.async.wait_group 1;");
        __syncthreads();

        if (i + 2 < NK) {
            const int k0 = (i + 2) * BK;
            __half* as = smh + ((i + 2) % NSTAGE) * STAGE_H;
            __half* bs = as + ASZ_H;
#pragma unroll
            for (int p = 0; p < 4; p++) {
                const int row = p * 32 + alr;
                cpa16h(as + row * ASTR + alc, Ag + (size_t)row * Kd + k0 + alc);
            }
#pragma unroll
            for (int p = 0; p < 4; p++) {
                const int row = p * 8 + blr;
                cpa16h(bs + row * BSTR + blc, Wg + (size_t)(k0 + row) * N + blc);
            }
            asm volatile("cp.async.commit_group;");
        }

        const __half* as = smh + (i % NSTAGE) * STAGE_H;
        const __half* bs = as + ASZ_H;

#pragma unroll
        for (int kk = 0; kk < BK; kk += 16) {
            uint32_t a[4][4], b[8][2];
#pragma unroll
            for (int mi = 0; mi < 4; mi++) {
                const int r = m0 + mi * 16 + (amat & 1) * 8 + arow;
                const int c = kk + (amat >> 1) * 8;
                const uint32_t addr = s2u(as + r * ASTR + c);
                asm volatile("ldmatrix.sync.aligned.m8n8.x4.shared.b16 {%0,%1,%2,%3}, [%4];"
                             : "=r"(a[mi][0]), "=r"(a[mi][1]), "=r"(a[mi][2]), "=r"(a[mi][3])
                             : "r"(addr));
            }
#pragma unroll
            for (int nf = 0; nf < 8; nf++) {
                const int r = kk + bmat * 8 + brow;
                const int c = n0 + nf * 8;
                const uint32_t addr = s2u(bs + r * BSTR + c);
                asm volatile("ldmatrix.sync.aligned.m8n8.x2.trans.shared.b16 {%0,%1}, [%2];"
                             : "=r"(b[nf][0]), "=r"(b[nf][1]) : "r"(addr));
            }
#pragma unroll
            for (int mi = 0; mi < 4; mi++)
#pragma unroll
                for (int nf = 0; nf < 8; nf++) {
                    asm volatile(
                        "mma.sync.aligned.m16n8k16.row.col.f32.f16.f16.f32 "
                        "{%0,%1,%2,%3}, {%4,%5,%6,%7}, {%8,%9}, {%0,%1,%2,%3};"
                        : "+f"(acc[mi][nf][0]), "+f"(acc[mi][nf][1]),
                          "+f"(acc[mi][nf][2]), "+f"(acc[mi][nf][3])
                        : "r"(a[mi][0]), "r"(a[mi][1]), "r"(a[mi][2]), "r"(a[mi][3]),
                          "r"(b[nf][0]), "r"(b[nf][1]));
                }
        }
    }

    const int gr = lane >> 2;
    const int gc = (lane & 3) * 2;
#pragma unroll
    for (int mi = 0; mi < 4; mi++) {
#pragma unroll
        for (int nf = 0; nf < 8; nf++) {
            const int col = bx * BN + n0 + nf * 8 + gc;
            const float b0 = bias[col], b1 = bias[col + 1];
            const int row0 = by * BM + m0 + mi * 16 + gr;

            float2 v0 = make_float2(acc[mi][nf][0] + b0, acc[mi][nf][1] + b1);
            float2 v1 = make_float2(acc[mi][nf][2] + b0, acc[mi][nf][3] + b1);
            if (relu) {
                v0.x = fmaxf(v0.x, 0.f); v0.y = fmaxf(v0.y, 0.f);
                v1.x = fmaxf(v1.x, 0.f); v1.y = fmaxf(v1.y, 0.f);
            }
            if (mode == 1 || (mode == 2 && col < 256)) {
                const int hstride = (mode == 2) ? 256 : N;
                *(__half2*)(Hout + (size_t)row0 * hstride + col)       = __floats2half2_rn(v0.x, v0.y);
                *(__half2*)(Hout + (size_t)(row0 + 8) * hstride + col) = __floats2half2_rn(v1.x, v1.y);
            } else {
                *(float2*)(Cout + (size_t)row0 * N + col)       = v0;
                *(float2*)(Cout + (size_t)(row0 + 8) * N + col) = v1;
            }
        }
    }
}

// ---------------- deformable sampling: 4 heads/warp, 4 channels/lane -------
// block 256 = 8 warps = 4 queries (2 warps/query). One 8B load covers a
// lane's 4 channels -> 16 warp-LDG per head (was 64).
__global__ __launch_bounds__(256, 8)
void deform_kernel(const float* __restrict__ qkv,
                   const __half* __restrict__ vh,
                   const float* __restrict__ ref,
                   __half* __restrict__ out) {
    const int warp = threadIdx.x >> 5;
    const int lane = threadIdx.x & 31;
    const int q = blockIdx.x * 4 + (warp >> 1);
    const int h = (warp & 1) * 4 + (lane >> 3);   // head 0..7
    const int cg = lane & 7;                       // channel group: 4 chans
    const int b = q / LQ_;

    // softmax over this head's 16 logits (redundant across the 8 lanes of a head)
    const float* lg = qkv + (size_t)q * NQKV + 512 + h * 16;
    float w[16];
    float mx = -1e30f;
#pragma unroll
    for (int i = 0; i < 16; i++) { w[i] = lg[i]; mx = fmaxf(mx, w[i]); }
    float s = 0.f;
#pragma unroll
    for (int i = 0; i < 16; i++) { w[i] = __expf(w[i] - mx); s += w[i]; }
    const float inv = 1.f / s;

    const float rx = ref[(size_t)q * 2 + 0];
    const float ry = ref[(size_t)q * 2 + 1];
    const float* offq = qkv + (size_t)q * NQKV + 256 + h * 32;

    float acc0 = 0.f, acc1 = 0.f, acc2 = 0.f, acc3 = 0.f;
#pragma unroll
    for (int l = 0; l < 4; l++) {
        const int Hl = d_scH[l], Wl = d_scW[l], st = d_scSt[l];
        const float invW = 1.f / (float)Wl, invH = 1.f / (float)Hl;
        const float Wm1 = (float)(Wl - 1), Hm1 = (float)(Hl - 1);
        const __half* vl = vh + (size_t)(b * LQ_ + st) * 256 + h * 32 + cg * 4;
#pragma unroll
        for (int k = 0; k < 4; k++) {
            const float ox = offq[l * 8 + k * 2 + 0];
            const float oy = offq[l * 8 + k * 2 + 1];
            const float ww = w[l * 4 + k] * inv;
            float x = (rx + ox * invW) * Wm1;
            float y = (ry + oy * invH) * Hm1;
            x = fminf(fmaxf(x, 0.f), Wm1);
            y = fminf(fmaxf(y, 0.f), Hm1);
            const float x0f = floorf(x), y0f = floorf(y);
            const int x0 = (int)x0f, y0 = (int)y0f;
            const int x1 = min(x0 + 1, Wl - 1), y1 = min(y0 + 1, Hl - 1);
            const float wx = x - x0f, wy = y - y0f;

            uint2 r00 = *(const uint2*)(vl + (size_t)(y0 * Wl + x0) * 256);
            uint2 r01 = *(const uint2*)(vl + (size_t)(y0 * Wl + x1) * 256);
            uint2 r10 = *(const uint2*)(vl + (size_t)(y1 * Wl + x0) * 256);
            uint2 r11 = *(const uint2*)(vl + (size_t)(y1 * Wl + x1) * 256);

            float2 a00 = __half22float2(*(__half2*)&r00.x);
            float2 b00 = __half22float2(*(__half2*)&r00.y);
            float2 a01 = __half22float2(*(__half2*)&r01.x);
            float2 b01 = __half22float2(*(__half2*)&r01.y);
            float2 a10 = __half22float2(*(__half2*)&r10.x);
            float2 b10 = __half22float2(*(__half2*)&r10.y);
            float2 a11 = __half22float2(*(__half2*)&r11.x);
            float2 b11 = __half22float2(*(__half2*)&r11.y);

            float top, bot;
            top = a00.x + wx * (a01.x - a00.x); bot = a10.x + wx * (a11.x - a10.x);
            acc0 = fmaf(ww, top + wy * (bot - top), acc0);
            top = a00.y + wx * (a01.y - a00.y); bot = a10.y + wx * (a11.y - a10.y);
            acc1 = fmaf(ww, top + wy * (bot - top), acc1);
            top = b00.x + wx * (b01.x - b00.x); bot = b10.x + wx * (b11.x - b10.x);
            acc2 = fmaf(ww, top + wy * (bot - top), acc2);
            top = b00.y + wx * (b01.y - b00.y); bot = b10.y + wx * (b11.y - b10.y);
            acc3 = fmaf(ww, top + wy * (bot - top), acc3);
        }
    }
    __half2 o0 = __floats2half2_rn(acc0, acc1);
    __half2 o1 = __floats2half2_rn(acc2, acc3);
    uint2 st2;
    st2.x = *(uint32_t*)&o0;
    st2.y = *(uint32_t*)&o1;
    *(uint2*)(out + (size_t)q * C_ + h * 32 + cg * 4) = st2;
}

// ---------------- fused residual + layernorm (fp32 + optional fp16) --------
__global__ void ln_kernel(const float* __restrict__ a, const float* __restrict__ b,
                          const float* __restrict__ gamma, const float* __restrict__ beta,
                          const float* __restrict__ pos,
                          float* __restrict__ out, __half* __restrict__ outH) {
    const int row = blockIdx.x * 8 + (threadIdx.x >> 5);
    const int lane = threadIdx.x & 31;
    const size_t base = (size_t)row * C_ + lane * 8;

    float vals[8];
    {
        float4 a0 = *(const float4*)(a + base);
        float4 a1 = *(const float4*)(a + base + 4);
        float4 b0 = *(const float4*)(b + base);
        float4 b1 = *(const float4*)(b + base + 4);
        vals[0] = a0.x + b0.x; vals[1] = a0.y + b0.y;
        vals[2] = a0.z + b0.z; vals[3] = a0.w + b0.w;
        vals[4] = a1.x + b1.x; vals[5] = a1.y + b1.y;
        vals[6] = a1.z + b1.z; vals[7] = a1.w + b1.w;
    }
    float s = 0.f;
#pragma unroll
    for (int i = 0; i < 8; i++) s += vals[i];
#pragma unroll
    for (int o = 16; o > 0; o >>= 1) s += __shfl_xor_sync(0xffffffffu, s, o);
    const float mean = s * (1.f / 256.f);
    float vs = 0.f;
#pragma unroll
    for (int i = 0; i < 8; i++) {
        const float dlt = vals[i] - mean;
        vs += dlt * dlt;
    }
#pragma unroll
    for (int o = 16; o > 0; o >>= 1) vs += __shfl_xor_sync(0xffffffffu, vs, o);
    const float rstd = rsqrtf(vs * (1.f / 256.f) + 1e-5f);

    const int c = lane * 8;
    float4 g0 = *(const float4*)(gamma + c);
    float4 g1 = *(const float4*)(gamma + c + 4);
    float4 t0 = *(const float4*)(beta + c);
    float4 t1 = *(const float4*)(beta + c + 4);
    float o[8];
    o[0] = (vals[0] - mean) * rstd * g0.x + t0.x;
    o[1] = (vals[1] - mean) * rstd * g0.y + t0.y;
    o[2] = (vals[2] - mean) * rstd * g0.z + t0.z;
    o[3] = (vals[3] - mean) * rstd * g0.w + t0.w;
    o[4] = (vals[4] - mean) * rstd * g1.x + t1.x;
    o[5] = (vals[5] - mean) * rstd * g1.y + t1.y;
    o[6] = (vals[6] - mean) * rstd * g1.z + t1.z;
    o[7] = (vals[7] - mean) * rstd * g1.w + t1.w;

    if (pos) {
        float4 p0 = *(const float4*)(pos + base);
        float4 p1 = *(const float4*)(pos + base + 4);
        o[0] += p0.x; o[1] += p0.y; o[2] += p0.z; o[3] += p0.w;
        o[4] += p1.x; o[5] += p1.y; o[6] += p1.z; o[7] += p1.w;
    }
    *(float4*)(out + base)     = make_float4(o[0], o[1], o[2], o[3]);
    *(float4*)(out + base + 4) = make_float4(o[4], o[5], o[6], o[7]);
    if (outH) {
        *(__half2*)(outH + base)     = __floats2half2_rn(o[0], o[1]);
        *(__half2*)(outH + base + 2) = __floats2half2_rn(o[2], o[3]);
        *(__half2*)(outH + base + 4) = __floats2half2_rn(o[4], o[5]);
        *(__half2*)(outH + base + 6) = __floats2half2_rn(o[6], o[7]);
    }
}

// ---------------- launch ----------------
extern "C" void kernel_launch(void* const* d_in, const int* in_sizes, int n_in,
                              void* d_out, int out_size) {
    const float* src  = (const float*)d_in[0];
    const float* pos  = (const float*)d_in[1];
    const float* ref  = (const float*)d_in[2];
    const float* Woff = (const float*)d_in[3];
    const float* boff = (const float*)d_in[4];
    const float* Wat  = (const float*)d_in[5];
    const float* bat  = (const float*)d_in[6];
    const float* Wv   = (const float*)d_in[7];
    const float* bv   = (const float*)d_in[8];
    const float* Wo   = (const float*)d_in[9];
    const float* bo   = (const float*)d_in[10];
    const float* W1   = (const float*)d_in[11];
    const float* b1   = (const float*)d_in[12];
    const float* W2   = (const float*)d_in[13];
    const float* b2   = (const float*)d_in[14];
    const float* n1s  = (const float*)d_in[15];
    const float* n1b  = (const float*)d_in[16];
    const float* n2s  = (const float*)d_in[17];
    const float* n2b  = (const float*)d_in[18];
    float* outp = (float*)d_out;

    float *xp, *qkv, *a, *x, *fbuf, *bq;
    __half *xpH, *vh, *sampH, *xH, *hH, *wq, *wo, *w1, *w2;
    cudaGetSymbolAddress((void**)&xp,    g_xp);
    cudaGetSymbolAddress((void**)&xpH,   g_xpH);
    cudaGetSymbolAddress((void**)&qkv,   g_qkv);
    cudaGetSymbolAddress((void**)&vh,    g_vh);
    cudaGetSymbolAddress((void**)&sampH, g_sampH);
    cudaGetSymbolAddress((void**)&a,     g_a);
    cudaGetSymbolAddress((void**)&x,     g_x);
    cudaGetSymbolAddress((void**)&xH,    g_xH);
    cudaGetSymbolAddress((void**)&hH,    g_hH);
    cudaGetSymbolAddress((void**)&fbuf,  g_f);
    cudaGetSymbolAddress((void**)&wq,    g_wq);
    cudaGetSymbolAddress((void**)&bq,    g_bq);
    cudaGetSymbolAddress((void**)&wo,    g_wo);
    cudaGetSymbolAddress((void**)&w1,    g_w1);
    cudaGetSymbolAddress((void**)&w2,    g_w2);

    cudaFuncSetAttribute(h16gemm_kernel,
                         cudaFuncAttributeMaxDynamicSharedMemorySize, GEMM_SMEM);

    // weight prep
    {
        const int nq = NL_ * C_ * NQKV;
        pack_qkv_kernel<<<(nq + 255) / 256, 256>>>(Wv, Woff, Wat, bv, boff, bat, wq, bq);
        const int n_wo = NL_ * C_ * C_ / 4;
        tohalf_kernel<<<(n_wo + 255) / 256, 256>>>(Wo, wo, n_wo);
        const int n_w1 = NL_ * C_ * FF_ / 4;
        tohalf_kernel<<<(n_w1 + 255) / 256, 256>>>(W1, w1, n_w1);
        const int n_w2 = NL_ * FF_ * C_ / 4;
        tohalf_kernel<<<(n_w2 + 255) / 256, 256>>>(W2, w2, n_w2);
    }

    const int n4 = M_ * C_ / 4;
    const dim3 gQKV(NQKV / BN, M_ / BM);
    const dim3 gN256(2, M_ / BM);
    const dim3 gN1024(8, M_ / BM);

    add0_kernel<<<(n4 + 255) / 256, 256>>>(src, pos, xp, xpH, n4);

    for (int i = 0; i < NL_; i++) {
        h16gemm_kernel<<<gQKV, 128, GEMM_SMEM>>>(xpH, wq + (size_t)i * C_ * NQKV,
                                                 bq + (size_t)i * NQKV, qkv, vh, NQKV, C_, 0, 2);
        deform_kernel<<<M_ / 4, 256>>>(qkv, vh, ref, sampH);
        h16gemm_kernel<<<gN256, 128, GEMM_SMEM>>>(sampH, wo + (size_t)i * C_ * C_,
                                                  bo + (size_t)i * C_, a, (__half*)nullptr, 256, C_, 0, 0);
        ln_kernel<<<M_ / 8, 256>>>(xp, a, n1s + (size_t)i * C_, n1b + (size_t)i * C_,
                                   (const float*)nullptr, x, xH);
        h16gemm_kernel<<<gN1024, 128, GEMM_SMEM>>>(xH, w1 + (size_t)i * C_ * FF_,
                                                   b1 + (size_t)i * FF_, (float*)nullptr, hH, FF_, C_, 1, 1);
        h16gemm_kernel<<<gN256, 128, GEMM_SMEM>>>(hH, w2 + (size_t)i * FF_ * C_,
                                                  b2 + (size_t)i * C_, fbuf, (__half*)nullptr, 256, FF_, 0, 0);
        if (i == NL_ - 1) {
            ln_kernel<<<M_ / 8, 256>>>(x, fbuf, n2s + (size_t)i * C_, n2b + (size_t)i * C_,
                                       (const float*)nullptr, outp, (__half*)nullptr);
        } else {
            ln_kernel<<<M_ / 8, 256>>>(x, fbuf, n2s + (size_t)i * C_, n2b + (size_t)i * C_,
                                       pos, xp, xpH);
        }
    }
    (void)in_sizes; (void)n_in; (void)out_size;
}

// round 12
// speedup vs baseline: 2.0962x; 1.1107x over previous
#include <cuda_runtime.h>
#include <cuda_fp16.h>
#include <math.h>
#include <stdint.h>

// ---------------- problem constants ----------------
#define B_     2
#define LQ_    21760
#define M_     (B_ * LQ_)      // 43520
#define C_     256
#define NHEAD_ 8
#define NS_    4
#define NL_    6
#define FF_    1024
#define NQKV   640             // 256 (v) + 256 (off) + 128 (att logits)

__device__ __constant__ int d_scH[4]   = {128, 64, 32, 16};
__device__ __constant__ int d_scW[4]   = {128, 64, 32, 16};
__device__ __constant__ int d_scSt[4]  = {0, 16384, 20480, 21504};

// ---------------- scratch (device globals; no allocation) ----------------
__device__ float  g_xp  [(size_t)M_ * C_];    // x+pos exact (residual 1)
__device__ __half g_xpH [(size_t)M_ * C_];    // fp16 xp (GEMM A)
__device__ float  g_qkv [(size_t)M_ * NQKV];  // off|logits fp32
__device__ __half g_vh  [(size_t)M_ * C_];    // fp16 value tensor
__device__ __half g_sampH[(size_t)M_ * C_];   // sampled value fp16 (Wo input)
__device__ float  g_a   [(size_t)M_ * C_];    // attn out proj fp32
__device__ float  g_x   [(size_t)M_ * C_];    // post-LN1 exact (residual 2)
__device__ __half g_xH  [(size_t)M_ * C_];    // fp16 post-LN1 (W1 input)
__device__ __half g_hH  [(size_t)M_ * FF_];   // FFN hidden fp16 (W2 input)
__device__ float  g_f   [(size_t)M_ * C_];    // FFN out fp32
// fp16 weights
__device__ __half g_wq  [(size_t)NL_ * C_ * NQKV];
__device__ float  g_bq  [(size_t)NL_ * NQKV];
__device__ __half g_wo  [(size_t)NL_ * C_ * C_];
__device__ __half g_w1  [(size_t)NL_ * C_ * FF_];
__device__ __half g_w2  [(size_t)NL_ * FF_ * C_];

// ---------------- weight prep ----------------
__global__ void tohalf_kernel(const float* __restrict__ src, __half* __restrict__ dst, int n4) {
    int i = blockIdx.x * blockDim.x + threadIdx.x;
    if (i >= n4) return;
    float4 v = ((const float4*)src)[i];
    __half2 h0 = __floats2half2_rn(v.x, v.y);
    __half2 h1 = __floats2half2_rn(v.z, v.w);
    ((__half2*)dst)[i * 2]     = h0;
    ((__half2*)dst)[i * 2 + 1] = h1;
}

__global__ void pack_qkv_kernel(const float* __restrict__ Wv, const float* __restrict__ Woff,
                                const float* __restrict__ Wat,
                                const float* __restrict__ bv, const float* __restrict__ boff,
                                const float* __restrict__ bat,
                                __half* __restrict__ wq, float* __restrict__ bq) {
    int idx = blockIdx.x * blockDim.x + threadIdx.x;
    const int total = NL_ * C_ * NQKV;
    if (idx < total) {
        const int c = idx % NQKV;
        const int k = (idx / NQKV) % C_;
        const int l = idx / (NQKV * C_);
        float v;
        if (c < 256)      v = Wv  [((size_t)l * C_ + k) * 256 + c];
        else if (c < 512) v = Woff[((size_t)l * C_ + k) * 256 + (c - 256)];
        else              v = Wat [((size_t)l * C_ + k) * 128 + (c - 512)];
        wq[idx] = __float2half(v);
    }
    if (idx < NL_ * NQKV) {
        const int c = idx % NQKV;
        const int l = idx / NQKV;
        float v;
        if (c < 256)      v = bv  [l * 256 + c];
        else if (c < 512) v = boff[l * 256 + (c - 256)];
        else              v = bat [l * 128 + (c - 512)];
        bq[idx] = v;
    }
}

// ---------------- layer-0 prep: xp = src + pos (fp32 + fp16) ----------------
__global__ void add0_kernel(const float* __restrict__ a, const float* __restrict__ b,
                            float* __restrict__ out, __half* __restrict__ outH, int n4) {
    int i = blockIdx.x * blockDim.x + threadIdx.x;
    if (i >= n4) return;
    float4 va = ((const float4*)a)[i];
    float4 vb = ((const float4*)b)[i];
    va.x += vb.x; va.y += vb.y; va.z += vb.z; va.w += vb.w;
    ((float4*)out)[i] = va;
    ((__half2*)outH)[i * 2]     = __floats2half2_rn(va.x, va.y);
    ((__half2*)outH)[i * 2 + 1] = __floats2half2_rn(va.z, va.w);
}

// ---------------- fp16 tensor-core GEMM (m16n8k16), cp.async 3-stage -------
#define BM 128
#define BN 128
#define BK 32
#define ASTR 40
#define BSTR 136
#define ASZ_H (BM * ASTR)
#define BSZ_H (BK * BSTR)
#define STAGE_H (ASZ_H + BSZ_H)
#define NSTAGE 3
#define GEMM_SMEM (NSTAGE * STAGE_H * 2)   // 56832 B

__device__ __forceinline__ void cpa16h(__half* dst, const __half* src) {
    uint32_t d = (uint32_t)__cvta_generic_to_shared(dst);
    asm volatile("cp.async.cg.shared.global [%0], [%1], 16;" :: "r"(d), "l"(src));
}
__device__ __forceinline__ uint32_t s2u(const __half* p) {
    return (uint32_t)__cvta_generic_to_shared(p);
}

// mode: 0 = fp32 out; 1 = fp16 out; 2 = qkv split (col<256 -> fp16 vh, else fp32)
__global__ __launch_bounds__(128, 2)
void h16gemm_kernel(const __half* __restrict__ A, const __half* __restrict__ W,
                    const float* __restrict__ bias, float* __restrict__ Cout,
                    __half* __restrict__ Hout,
                    int N, int Kd, int relu, int mode) {
    extern __shared__ __align__(16) __half smh[];

    const int tid  = threadIdx.x;
    const int warp = tid >> 5;
    const int lane = tid & 31;
    const int m0 = (warp >> 1) * 64;
    const int n0 = (warp & 1) * 64;
    const int bx = blockIdx.x, by = blockIdx.y;

    const int alr = tid >> 2;
    const int alc = (tid & 3) * 8;
    const int blr = tid >> 4;
    const int blc = (tid & 15) * 8;

    const __half* Ag = A + (size_t)(by * BM) * Kd;
    const __half* Wg = W + (size_t)bx * BN;

    float acc[4][8][4];
#pragma unroll
    for (int mi = 0; mi < 4; mi++)
#pragma unroll
        for (int nf = 0; nf < 8; nf++)
#pragma unroll
            for (int r = 0; r < 4; r++) acc[mi][nf][r] = 0.f;

    const int NK = Kd / BK;

#pragma unroll
    for (int s = 0; s < 2; s++) {
        if (s < NK) {
            __half* as = smh + s * STAGE_H;
            __half* bs = as + ASZ_H;
            const int k0 = s * BK;
#pragma unroll
            for (int p = 0; p < 4; p++) {
                const int row = p * 32 + alr;
                cpa16h(as + row * ASTR + alc, Ag + (size_t)row * Kd + k0 + alc);
            }
#pragma unroll
            for (int p = 0; p < 4; p++) {
                const int row = p * 8 + blr;
                cpa16h(bs + row * BSTR + blc, Wg + (size_t)(k0 + row) * N + blc);
            }
            asm volatile("cp.async.commit_group;");
        }
    }

    const int amat = lane >> 3;
    const int arow = lane & 7;
    const int bl   = lane & 15;
    const int bmat = bl >> 3;
    const int brow = bl & 7;

    for (int i = 0; i < NK; i++) {
        asm volatile("cp.async.wait_group 1;");
        __syncthreads();

        if (i + 2 < NK) {
            const int k0 = (i + 2) * BK;
            __half* as = smh + ((i + 2) % NSTAGE) * STAGE_H;
            __half* bs = as + ASZ_H;
#pragma unroll
            for (int p = 0; p < 4; p++) {
                const int row = p * 32 + alr;
                cpa16h(as + row * ASTR + alc, Ag + (size_t)row * Kd + k0 + alc);
            }
#pragma unroll
            for (int p = 0; p < 4; p++) {
                const int row = p * 8 + blr;
                cpa16h(bs + row * BSTR + blc, Wg + (size_t)(k0 + row) * N + blc);
            }
            asm volatile("cp.async.commit_group;");
        }

        const __half* as = smh + (i % NSTAGE) * STAGE_H;
        const __half* bs = as + ASZ_H;

#pragma unroll
        for (int kk = 0; kk < BK; kk += 16) {
            uint32_t a[4][4], b[8][2];
#pragma unroll
            for (int mi = 0; mi < 4; mi++) {
                const int r = m0 + mi * 16 + (amat & 1) * 8 + arow;
                const int c = kk + (amat >> 1) * 8;
                const uint32_t addr = s2u(as + r * ASTR + c);
                asm volatile("ldmatrix.sync.aligned.m8n8.x4.shared.b16 {%0,%1,%2,%3}, [%4];"
                             : "=r"(a[mi][0]), "=r"(a[mi][1]), "=r"(a[mi][2]), "=r"(a[mi][3])
                             : "r"(addr));
            }
#pragma unroll
            for (int nf = 0; nf < 8; nf++) {
                const int r = kk + bmat * 8 + brow;
                const int c = n0 + nf * 8;
                const uint32_t addr = s2u(bs + r * BSTR + c);
                asm volatile("ldmatrix.sync.aligned.m8n8.x2.trans.shared.b16 {%0,%1}, [%2];"
                             : "=r"(b[nf][0]), "=r"(b[nf][1]) : "r"(addr));
            }
#pragma unroll
            for (int mi = 0; mi < 4; mi++)
#pragma unroll
                for (int nf = 0; nf < 8; nf++) {
                    asm volatile(
                        "mma.sync.aligned.m16n8k16.row.col.f32.f16.f16.f32 "
                        "{%0,%1,%2,%3}, {%4,%5,%6,%7}, {%8,%9}, {%0,%1,%2,%3};"
                        : "+f"(acc[mi][nf][0]), "+f"(acc[mi][nf][1]),
                          "+f"(acc[mi][nf][2]), "+f"(acc[mi][nf][3])
                        : "r"(a[mi][0]), "r"(a[mi][1]), "r"(a[mi][2]), "r"(a[mi][3]),
                          "r"(b[nf][0]), "r"(b[nf][1]));
                }
        }
    }

    const int gr = lane >> 2;
    const int gc = (lane & 3) * 2;
#pragma unroll
    for (int mi = 0; mi < 4; mi++) {
#pragma unroll
        for (int nf = 0; nf < 8; nf++) {
            const int col = bx * BN + n0 + nf * 8 + gc;
            const float b0 = bias[col], b1 = bias[col + 1];
            const int row0 = by * BM + m0 + mi * 16 + gr;

            float2 v0 = make_float2(acc[mi][nf][0] + b0, acc[mi][nf][1] + b1);
            float2 v1 = make_float2(acc[mi][nf][2] + b0, acc[mi][nf][3] + b1);
            if (relu) {
                v0.x = fmaxf(v0.x, 0.f); v0.y = fmaxf(v0.y, 0.f);
                v1.x = fmaxf(v1.x, 0.f); v1.y = fmaxf(v1.y, 0.f);
            }
            if (mode == 1 || (mode == 2 && col < 256)) {
                const int hstride = (mode == 2) ? 256 : N;
                *(__half2*)(Hout + (size_t)row0 * hstride + col)       = __floats2half2_rn(v0.x, v0.y);
                *(__half2*)(Hout + (size_t)(row0 + 8) * hstride + col) = __floats2half2_rn(v1.x, v1.y);
            } else {
                *(float2*)(Cout + (size_t)row0 * N + col)       = v0;
                *(float2*)(Cout + (size_t)(row0 + 8) * N + col) = v1;
            }
        }
    }
}

// ---------------- deformable sampling v3: warp per query -------------------
// 8 heads/warp; lane = (head, cg) with cg in 0..3, 8 channels/lane (16B LDG).
// Softmax: each lane computes 4 exps, quad-shfl assembles -> 8x less MUFU.
__global__ __launch_bounds__(256, 4)
void deform_kernel(const float* __restrict__ qkv,
                   const __half* __restrict__ vh,
                   const float* __restrict__ ref,
                   __half* __restrict__ out) {
    const int warp = threadIdx.x >> 5;
    const int lane = threadIdx.x & 31;
    const int q = blockIdx.x * 8 + warp;
    const int h = lane >> 2;          // head 0..7
    const int cg = lane & 3;          // channel group of 8
    const int b = q / LQ_;

    // --- softmax over this head's 16 logits, split across the 4 lanes ---
    const float* lg = qkv + (size_t)q * NQKV + 512 + h * 16;
    const float4 lv = *(const float4*)(lg + cg * 4);
    float mx = fmaxf(fmaxf(lv.x, lv.y), fmaxf(lv.z, lv.w));
    mx = fmaxf(mx, __shfl_xor_sync(0xffffffffu, mx, 1));
    mx = fmaxf(mx, __shfl_xor_sync(0xffffffffu, mx, 2));
    float e[4];
    e[0] = __expf(lv.x - mx);
    e[1] = __expf(lv.y - mx);
    e[2] = __expf(lv.z - mx);
    e[3] = __expf(lv.w - mx);
    float s = e[0] + e[1] + e[2] + e[3];
    s += __shfl_xor_sync(0xffffffffu, s, 1);
    s += __shfl_xor_sync(0xffffffffu, s, 2);
    const float inv = 1.f / s;
    const int quad = lane & ~3;

    const float rx = ref[(size_t)q * 2 + 0];
    const float ry = ref[(size_t)q * 2 + 1];
    const float* offq = qkv + (size_t)q * NQKV + 256 + h * 32;

    float acc[8];
#pragma unroll
    for (int c = 0; c < 8; c++) acc[c] = 0.f;

#pragma unroll
    for (int l = 0; l < 4; l++) {
        const int Hl = d_scH[l], Wl = d_scW[l], st = d_scSt[l];
        const float invW = 1.f / (float)Wl, invH = 1.f / (float)Hl;
        const float Wm1 = (float)(Wl - 1), Hm1 = (float)(Hl - 1);
        const __half* vl = vh + (size_t)(b * LQ_ + st) * 256 + h * 32 + cg * 8;
#pragma unroll
        for (int k = 0; k < 4; k++) {
            const int idx = l * 4 + k;
            const float2 oxy = *(const float2*)(offq + idx * 2);
            const float ww = __shfl_sync(0xffffffffu, e[idx & 3], quad + (idx >> 2)) * inv;
            float x = (rx + oxy.x * invW) * Wm1;
            float y = (ry + oxy.y * invH) * Hm1;
            x = fminf(fmaxf(x, 0.f), Wm1);
            y = fminf(fmaxf(y, 0.f), Hm1);
            const float x0f = floorf(x), y0f = floorf(y);
            const int x0 = (int)x0f, y0 = (int)y0f;
            const int x1 = min(x0 + 1, Wl - 1), y1 = min(y0 + 1, Hl - 1);
            const float wx = x - x0f, wy = y - y0f;

            uint4 r00 = *(const uint4*)(vl + (size_t)(y0 * Wl + x0) * 256);
            uint4 r01 = *(const uint4*)(vl + (size_t)(y0 * Wl + x1) * 256);
            uint4 r10 = *(const uint4*)(vl + (size_t)(y1 * Wl + x0) * 256);
            uint4 r11 = *(const uint4*)(vl + (size_t)(y1 * Wl + x1) * 256);

            const uint32_t* p00 = (const uint32_t*)&r00;
            const uint32_t* p01 = (const uint32_t*)&r01;
            const uint32_t* p10 = (const uint32_t*)&r10;
            const uint32_t* p11 = (const uint32_t*)&r11;
#pragma unroll
            for (int c2 = 0; c2 < 4; c2++) {
                float2 f00 = __half22float2(*(const __half2*)&p00[c2]);
                float2 f01 = __half22float2(*(const __half2*)&p01[c2]);
                float2 f10 = __half22float2(*(const __half2*)&p10[c2]);
                float2 f11 = __half22float2(*(const __half2*)&p11[c2]);
                float top, bot;
                top = f00.x + wx * (f01.x - f00.x);
                bot = f10.x + wx * (f11.x - f10.x);
                acc[c2 * 2]     = fmaf(ww, top + wy * (bot - top), acc[c2 * 2]);
                top = f00.y + wx * (f01.y - f00.y);
                bot = f10.y + wx * (f11.y - f10.y);
                acc[c2 * 2 + 1] = fmaf(ww, top + wy * (bot - top), acc[c2 * 2 + 1]);
            }
        }
    }

    uint4 st4;
    uint32_t* sp = (uint32_t*)&st4;
#pragma unroll
    for (int c2 = 0; c2 < 4; c2++) {
        __half2 hh = __floats2half2_rn(acc[c2 * 2], acc[c2 * 2 + 1]);
        sp[c2] = *(uint32_t*)&hh;
    }
    *(uint4*)(out + (size_t)q * C_ + h * 32 + cg * 8) = st4;
}

// ---------------- fused residual + layernorm (fp32 + optional fp16) --------
__global__ void ln_kernel(const float* __restrict__ a, const float* __restrict__ b,
                          const float* __restrict__ gamma, const float* __restrict__ beta,
                          const float* __restrict__ pos,
                          float* __restrict__ out, __half* __restrict__ outH) {
    const int row = blockIdx.x * 8 + (threadIdx.x >> 5);
    const int lane = threadIdx.x & 31;
    const size_t base = (size_t)row * C_ + lane * 8;

    float vals[8];
    {
        float4 a0 = *(const float4*)(a + base);
        float4 a1 = *(const float4*)(a + base + 4);
        float4 b0 = *(const float4*)(b + base);
        float4 b1 = *(const float4*)(b + base + 4);
        vals[0] = a0.x + b0.x; vals[1] = a0.y + b0.y;
        vals[2] = a0.z + b0.z; vals[3] = a0.w + b0.w;
        vals[4] = a1.x + b1.x; vals[5] = a1.y + b1.y;
        vals[6] = a1.z + b1.z; vals[7] = a1.w + b1.w;
    }
    float s = 0.f;
#pragma unroll
    for (int i = 0; i < 8; i++) s += vals[i];
#pragma unroll
    for (int o = 16; o > 0; o >>= 1) s += __shfl_xor_sync(0xffffffffu, s, o);
    const float mean = s * (1.f / 256.f);
    float vs = 0.f;
#pragma unroll
    for (int i = 0; i < 8; i++) {
        const float dlt = vals[i] - mean;
        vs += dlt * dlt;
    }
#pragma unroll
    for (int o = 16; o > 0; o >>= 1) vs += __shfl_xor_sync(0xffffffffu, vs, o);
    const float rstd = rsqrtf(vs * (1.f / 256.f) + 1e-5f);

    const int c = lane * 8;
    float4 g0 = *(const float4*)(gamma + c);
    float4 g1 = *(const float4*)(gamma + c + 4);
    float4 t0 = *(const float4*)(beta + c);
    float4 t1 = *(const float4*)(beta + c + 4);
    float o[8];
    o[0] = (vals[0] - mean) * rstd * g0.x + t0.x;
    o[1] = (vals[1] - mean) * rstd * g0.y + t0.y;
    o[2] = (vals[2] - mean) * rstd * g0.z + t0.z;
    o[3] = (vals[3] - mean) * rstd * g0.w + t0.w;
    o[4] = (vals[4] - mean) * rstd * g1.x + t1.x;
    o[5] = (vals[5] - mean) * rstd * g1.y + t1.y;
    o[6] = (vals[6] - mean) * rstd * g1.z + t1.z;
    o[7] = (vals[7] - mean) * rstd * g1.w + t1.w;

    if (pos) {
        float4 p0 = *(const float4*)(pos + base);
        float4 p1 = *(const float4*)(pos + base + 4);
        o[0] += p0.x; o[1] += p0.y; o[2] += p0.z; o[3] += p0.w;
        o[4] += p1.x; o[5] += p1.y; o[6] += p1.z; o[7] += p1.w;
    }
    *(float4*)(out + base)     = make_float4(o[0], o[1], o[2], o[3]);
    *(float4*)(out + base + 4) = make_float4(o[4], o[5], o[6], o[7]);
    if (outH) {
        *(__half2*)(outH + base)     = __floats2half2_rn(o[0], o[1]);
        *(__half2*)(outH + base + 2) = __floats2half2_rn(o[2], o[3]);
        *(__half2*)(outH + base + 4) = __floats2half2_rn(o[4], o[5]);
        *(__half2*)(outH + base + 6) = __floats2half2_rn(o[6], o[7]);
    }
}

// ---------------- launch ----------------
extern "C" void kernel_launch(void* const* d_in, const int* in_sizes, int n_in,
                              void* d_out, int out_size) {
    const float* src  = (const float*)d_in[0];
    const float* pos  = (const float*)d_in[1];
    const float* ref  = (const float*)d_in[2];
    const float* Woff = (const float*)d_in[3];
    const float* boff = (const float*)d_in[4];
    const float* Wat  = (const float*)d_in[5];
    const float* bat  = (const float*)d_in[6];
    const float* Wv   = (const float*)d_in[7];
    const float* bv   = (const float*)d_in[8];
    const float* Wo   = (const float*)d_in[9];
    const float* bo   = (const float*)d_in[10];
    const float* W1   = (const float*)d_in[11];
    const float* b1   = (const float*)d_in[12];
    const float* W2   = (const float*)d_in[13];
    const float* b2   = (const float*)d_in[14];
    const float* n1s  = (const float*)d_in[15];
    const float* n1b  = (const float*)d_in[16];
    const float* n2s  = (const float*)d_in[17];
    const float* n2b  = (const float*)d_in[18];
    float* outp = (float*)d_out;

    float *xp, *qkv, *a, *x, *fbuf, *bq;
    __half *xpH, *vh, *sampH, *xH, *hH, *wq, *wo, *w1, *w2;
    cudaGetSymbolAddress((void**)&xp,    g_xp);
    cudaGetSymbolAddress((void**)&xpH,   g_xpH);
    cudaGetSymbolAddress((void**)&qkv,   g_qkv);
    cudaGetSymbolAddress((void**)&vh,    g_vh);
    cudaGetSymbolAddress((void**)&sampH, g_sampH);
    cudaGetSymbolAddress((void**)&a,     g_a);
    cudaGetSymbolAddress((void**)&x,     g_x);
    cudaGetSymbolAddress((void**)&xH,    g_xH);
    cudaGetSymbolAddress((void**)&hH,    g_hH);
    cudaGetSymbolAddress((void**)&fbuf,  g_f);
    cudaGetSymbolAddress((void**)&wq,    g_wq);
    cudaGetSymbolAddress((void**)&bq,    g_bq);
    cudaGetSymbolAddress((void**)&wo,    g_wo);
    cudaGetSymbolAddress((void**)&w1,    g_w1);
    cudaGetSymbolAddress((void**)&w2,    g_w2);

    cudaFuncSetAttribute(h16gemm_kernel,
                         cudaFuncAttributeMaxDynamicSharedMemorySize, GEMM_SMEM);

    // weight prep
    {
        const int nq = NL_ * C_ * NQKV;
        pack_qkv_kernel<<<(nq + 255) / 256, 256>>>(Wv, Woff, Wat, bv, boff, bat, wq, bq);
        const int n_wo = NL_ * C_ * C_ / 4;
        tohalf_kernel<<<(n_wo + 255) / 256, 256>>>(Wo, wo, n_wo);
        const int n_w1 = NL_ * C_ * FF_ / 4;
        tohalf_kernel<<<(n_w1 + 255) / 256, 256>>>(W1, w1, n_w1);
        const int n_w2 = NL_ * FF_ * C_ / 4;
        tohalf_kernel<<<(n_w2 + 255) / 256, 256>>>(W2, w2, n_w2);
    }

    const int n4 = M_ * C_ / 4;
    const dim3 gQKV(NQKV / BN, M_ / BM);
    const dim3 gN256(2, M_ / BM);
    const dim3 gN1024(8, M_ / BM);

    add0_kernel<<<(n4 + 255) / 256, 256>>>(src, pos, xp, xpH, n4);

    for (int i = 0; i < NL_; i++) {
        h16gemm_kernel<<<gQKV, 128, GEMM_SMEM>>>(xpH, wq + (size_t)i * C_ * NQKV,
                                                 bq + (size_t)i * NQKV, qkv, vh, NQKV, C_, 0, 2);
        deform_kernel<<<M_ / 8, 256>>>(qkv, vh, ref, sampH);
        h16gemm_kernel<<<gN256, 128, GEMM_SMEM>>>(sampH, wo + (size_t)i * C_ * C_,
                                                  bo + (size_t)i * C_, a, (__half*)nullptr, 256, C_, 0, 0);
        ln_kernel<<<M_ / 8, 256>>>(xp, a, n1s + (size_t)i * C_, n1b + (size_t)i * C_,
                                   (const float*)nullptr, x, xH);
        h16gemm_kernel<<<gN1024, 128, GEMM_SMEM>>>(xH, w1 + (size_t)i * C_ * FF_,
                                                   b1 + (size_t)i * FF_, (float*)nullptr, hH, FF_, C_, 1, 1);
        h16gemm_kernel<<<gN256, 128, GEMM_SMEM>>>(hH, w2 + (size_t)i * FF_ * C_,
                                                  b2 + (size_t)i * C_, fbuf, (__half*)nullptr, 256, FF_, 0, 0);
        if (i == NL_ - 1) {
            ln_kernel<<<M_ / 8, 256>>>(x, fbuf, n2s + (size_t)i * C_, n2b + (size_t)i * C_,
                                       (const float*)nullptr, outp, (__half*)nullptr);
        } else {
            ln_kernel<<<M_ / 8, 256>>>(x, fbuf, n2s + (size_t)i * C_, n2b + (size_t)i * C_,
                                       pos, xp, xpH);
        }
    }
    (void)in_sizes; (void)n_in; (void)out_size;
}